// round 3
// baseline (speedup 1.0000x reference)
#include <cuda_runtime.h>
#include <math.h>
#include <stdio.h>

#define L_DIM 1024
#define E_DIM 768
#define P_DIM 128
#define H_DIM 16
#define HD_DIM 48
#define DEPTH 8
#define MLP_DIM 3072
#define FREQ 256

// ---------------- scratch (device globals; no allocation allowed) ----------
__device__ float g_x[L_DIM * E_DIM];
__device__ float g_h[L_DIM * E_DIM];
__device__ float g_qkv[L_DIM * 3 * E_DIM];
__device__ float g_y[L_DIM * E_DIM];
__device__ float g_t1[L_DIM * MLP_DIM];
__device__ float g_S[(size_t)H_DIM * L_DIM * L_DIM];   // 64 MB scores/probs
__device__ float g_bh[(size_t)H_DIM * L_DIM * L_DIM];  // 64 MB attention bias
__device__ float g_hidden[E_DIM];
__device__ float g_cs[E_DIM];
__device__ float g_ada[DEPTH * 6 * E_DIM + 2 * E_DIM];

// ---------------- small kernels --------------------------------------------
__global__ void k_copy(const float* __restrict__ src, float* __restrict__ dst, int n) {
    int i = blockIdx.x * blockDim.x + threadIdx.x;
    if (i < n) dst[i] = src[i];
}

__device__ __forceinline__ float silu_f(float x) { return x / (1.0f + expf(-x)); }
__device__ __forceinline__ float gelu_f(float v) {
    float c = v + 0.044715f * v * v * v;
    return 0.5f * v * (1.0f + tanhf(0.7978845608028654f * c));
}

__global__ void k_time1(const float* __restrict__ t,
                        const float* __restrict__ w,   // (E, 256)
                        const float* __restrict__ b) {
    int i = blockIdx.x * blockDim.x + threadIdx.x;
    if (i >= E_DIM) return;
    float tv = t[0];
    float acc = 0.0f;
    const float kfac = -9.210340371976184f / 128.0f;  // -log(10000)/half
    for (int j = 0; j < 128; j++) {
        float f = expf(kfac * (float)j);
        float a = tv * f;
        acc += cosf(a) * w[i * 256 + j] + sinf(a) * w[i * 256 + 128 + j];
    }
    float h = acc + b[i];
    g_hidden[i] = silu_f(h);
}

__global__ void k_time2(const float* __restrict__ w,  // (E, E)
                        const float* __restrict__ b) {
    int i = blockIdx.x * blockDim.x + threadIdx.x;
    if (i >= E_DIM) return;
    float acc = 0.0f;
    for (int j = 0; j < E_DIM; j++) acc += g_hidden[j] * w[i * E_DIM + j];
    g_cs[i] = silu_f(acc + b[i]);
}

// ada for all 8 blocks + final, computed once
__global__ __launch_bounds__(256) void k_ada(const float* __restrict__ aw,   // (D,6E,E)
                                             const float* __restrict__ ab,   // (D,6E)
                                             const float* __restrict__ fw,   // (2E,E)
                                             const float* __restrict__ fb) { // (2E)
    __shared__ float scs[E_DIM];
    for (int i = threadIdx.x; i < E_DIM; i += 256) scs[i] = g_cs[i];
    __syncthreads();
    int o = blockIdx.x * 256 + threadIdx.x;
    const int NB = DEPTH * 6 * E_DIM;  // 36864
    if (o >= NB + 2 * E_DIM) return;
    const float* w;
    float bias;
    if (o < NB) {
        w = aw + (size_t)o * E_DIM;
        bias = ab[o];
    } else {
        int j = o - NB;
        w = fw + (size_t)j * E_DIM;
        bias = fb[j];
    }
    float acc = 0.0f;
    for (int j = 0; j < E_DIM; j++) acc += scs[j] * w[j];
    g_ada[o] = acc + bias;
}

// bh[h,l,m] = (LN(bias[l,m,:])*g+beta) dot p2s_w[h,:]
__global__ __launch_bounds__(256) void k_bh(const float* __restrict__ bias,
                                            const float* __restrict__ gam,
                                            const float* __restrict__ bet,
                                            const float* __restrict__ pw) {
    __shared__ float sw[H_DIM][P_DIM];
    __shared__ float sg[P_DIM], sb[P_DIM];
    for (int i = threadIdx.x; i < H_DIM * P_DIM; i += 256) sw[i >> 7][i & 127] = pw[i];
    if (threadIdx.x < P_DIM) { sg[threadIdx.x] = gam[threadIdx.x]; sb[threadIdx.x] = bet[threadIdx.x]; }
    __syncthreads();
    int warp = threadIdx.x >> 5, lane = threadIdx.x & 31;
    size_t idx = (size_t)blockIdx.x * 8 + warp;  // l*L + m
    const float* src = bias + idx * P_DIM;
    float v[4];
#pragma unroll
    for (int i = 0; i < 4; i++) v[i] = src[lane + 32 * i];
    float s = v[0] + v[1] + v[2] + v[3];
#pragma unroll
    for (int o = 16; o; o >>= 1) s += __shfl_xor_sync(0xffffffffu, s, o);
    float mean = s * (1.0f / 128.0f);
    float q = 0.0f;
#pragma unroll
    for (int i = 0; i < 4; i++) { float d = v[i] - mean; q += d * d; }
#pragma unroll
    for (int o = 16; o; o >>= 1) q += __shfl_xor_sync(0xffffffffu, q, o);
    float rs = rsqrtf(q * (1.0f / 128.0f) + 1e-6f);
    float n[4];
#pragma unroll
    for (int i = 0; i < 4; i++) {
        int p = lane + 32 * i;
        n[i] = (v[i] - mean) * rs * sg[p] + sb[p];
    }
#pragma unroll
    for (int h = 0; h < H_DIM; h++) {
        float a = n[0] * sw[h][lane] + n[1] * sw[h][lane + 32] +
                  n[2] * sw[h][lane + 64] + n[3] * sw[h][lane + 96];
#pragma unroll
        for (int o = 16; o; o >>= 1) a += __shfl_xor_sync(0xffffffffu, a, o);
        if (lane == 0) g_bh[(size_t)h * L_DIM * L_DIM + idx] = a;
    }
}

// LN(x) modulated -> g_h.  sh = g_ada[ada_off..], sc = g_ada[ada_off+E..]
__global__ __launch_bounds__(256) void k_lnmod(const float* __restrict__ x, int ada_off) {
    int l = blockIdx.x;
    int t = threadIdx.x;
    const float* row = x + (size_t)l * E_DIM;
    float v0 = row[t], v1 = row[t + 256], v2 = row[t + 512];
    __shared__ float red[8];
    __shared__ float smean, srs;
    int lane = t & 31, warp = t >> 5;
    float s = v0 + v1 + v2;
#pragma unroll
    for (int o = 16; o; o >>= 1) s += __shfl_xor_sync(0xffffffffu, s, o);
    if (lane == 0) red[warp] = s;
    __syncthreads();
    if (t == 0) {
        float tot = 0;
        for (int i = 0; i < 8; i++) tot += red[i];
        smean = tot * (1.0f / 768.0f);
    }
    __syncthreads();
    float mean = smean;
    float d0 = v0 - mean, d1 = v1 - mean, d2 = v2 - mean;
    float q = d0 * d0 + d1 * d1 + d2 * d2;
#pragma unroll
    for (int o = 16; o; o >>= 1) q += __shfl_xor_sync(0xffffffffu, q, o);
    __syncthreads();
    if (lane == 0) red[warp] = q;
    __syncthreads();
    if (t == 0) {
        float tot = 0;
        for (int i = 0; i < 8; i++) tot += red[i];
        srs = rsqrtf(tot * (1.0f / 768.0f) + 1e-6f);
    }
    __syncthreads();
    float rs = srs;
    const float* sh = g_ada + ada_off;
    const float* sc = g_ada + ada_off + E_DIM;
    float* out = g_h + (size_t)l * E_DIM;
    out[t]       = d0 * rs * (1.0f + sc[t])       + sh[t];
    out[t + 256] = d1 * rs * (1.0f + sc[t + 256]) + sh[t + 256];
    out[t + 512] = d2 * rs * (1.0f + sc[t + 512]) + sh[t + 512];
}

// ---------------- GEMM: C[M,N] = A[M,K] @ W[N,K]^T (+bias, act, residual) --
// ACT: 0 = none, 1 = gelu
// If res != nullptr: C[idx] = res[idx] + gate[col] * val   (residual-gated)
template <int ACT>
__global__ __launch_bounds__(256) void gemm_nt(const float* __restrict__ A,
                                               const float* __restrict__ W,
                                               const float* __restrict__ bias,
                                               const float* __restrict__ res,
                                               const float* __restrict__ gate,
                                               float* __restrict__ C,
                                               int M, int N, int K, int lda) {
    __shared__ float As[16][68];
    __shared__ float Ws[16][68];
    int bm = blockIdx.y * 64, bn = blockIdx.x * 64;
    int tid = threadIdx.x;
    int tm = (tid >> 4) << 2, tn = (tid & 15) << 2;
    int lm = tid >> 2;
    int lk = (tid & 3) << 2;
    float acc[4][4] = {};
    for (int k0 = 0; k0 < K; k0 += 16) {
        float4 av = *(const float4*)&A[(size_t)(bm + lm) * lda + k0 + lk];
        float4 wv = *(const float4*)&W[(size_t)(bn + lm) * K + k0 + lk];
        As[lk + 0][lm] = av.x; As[lk + 1][lm] = av.y; As[lk + 2][lm] = av.z; As[lk + 3][lm] = av.w;
        Ws[lk + 0][lm] = wv.x; Ws[lk + 1][lm] = wv.y; Ws[lk + 2][lm] = wv.z; Ws[lk + 3][lm] = wv.w;
        __syncthreads();
#pragma unroll
        for (int k = 0; k < 16; k++) {
            float4 a = *(const float4*)&As[k][tm];
            float4 b = *(const float4*)&Ws[k][tn];
            acc[0][0] += a.x * b.x; acc[0][1] += a.x * b.y; acc[0][2] += a.x * b.z; acc[0][3] += a.x * b.w;
            acc[1][0] += a.y * b.x; acc[1][1] += a.y * b.y; acc[1][2] += a.y * b.z; acc[1][3] += a.y * b.w;
            acc[2][0] += a.z * b.x; acc[2][1] += a.z * b.y; acc[2][2] += a.z * b.z; acc[2][3] += a.z * b.w;
            acc[3][0] += a.w * b.x; acc[3][1] += a.w * b.y; acc[3][2] += a.w * b.z; acc[3][3] += a.w * b.w;
        }
        __syncthreads();
    }
    float b4[4] = {0, 0, 0, 0};
    if (bias) {
#pragma unroll
        for (int j = 0; j < 4; j++) b4[j] = bias[bn + tn + j];
    }
    float gt[4] = {0, 0, 0, 0};
    if (res) {
#pragma unroll
        for (int j = 0; j < 4; j++) gt[j] = gate[bn + tn + j];
    }
#pragma unroll
    for (int i = 0; i < 4; i++) {
        size_t off = (size_t)(bm + tm + i) * N + bn + tn;
        float* cr = C + off;
#pragma unroll
        for (int j = 0; j < 4; j++) {
            float v = acc[i][j] + b4[j];
            if (ACT == 1) v = gelu_f(v);
            if (res) v = res[off + j] + gt[j] * v;
            cr[j] = v;
        }
    }
}

// ---------------- attention ------------------------------------------------
__global__ __launch_bounds__(256) void attn_scores() {
    const float scale = 0.14433756729740643f;  // 48^-0.5
    int h = blockIdx.z;
    int l0 = blockIdx.y * 64, m0 = blockIdx.x * 64;
    __shared__ float Qs[HD_DIM][65];
    __shared__ float Ks[HD_DIM][65];
    for (int i = threadIdx.x; i < 64 * 48; i += 256) {
        int r = i / 48, c = i % 48;
        Qs[c][r] = g_qkv[(size_t)(l0 + r) * 2304 + h * 144 + c];
        Ks[c][r] = g_qkv[(size_t)(m0 + r) * 2304 + h * 144 + 48 + c];
    }
    __syncthreads();
    int tl = (threadIdx.x >> 4) << 2, tm = (threadIdx.x & 15) << 2;
    float acc[4][4] = {};
#pragma unroll 4
    for (int c = 0; c < 48; c++) {
        float q0 = Qs[c][tl], q1 = Qs[c][tl + 1], q2 = Qs[c][tl + 2], q3 = Qs[c][tl + 3];
        float k0 = Ks[c][tm], k1 = Ks[c][tm + 1], k2 = Ks[c][tm + 2], k3 = Ks[c][tm + 3];
        acc[0][0] += q0 * k0; acc[0][1] += q0 * k1; acc[0][2] += q0 * k2; acc[0][3] += q0 * k3;
        acc[1][0] += q1 * k0; acc[1][1] += q1 * k1; acc[1][2] += q1 * k2; acc[1][3] += q1 * k3;
        acc[2][0] += q2 * k0; acc[2][1] += q2 * k1; acc[2][2] += q2 * k2; acc[2][3] += q2 * k3;
        acc[3][0] += q3 * k0; acc[3][1] += q3 * k1; acc[3][2] += q3 * k2; acc[3][3] += q3 * k3;
    }
    size_t base = (size_t)h * L_DIM * L_DIM;
#pragma unroll
    for (int i = 0; i < 4; i++)
#pragma unroll
        for (int j = 0; j < 4; j++) {
            size_t idx = base + (size_t)(l0 + tl + i) * L_DIM + m0 + tm + j;
            g_S[idx] = acc[i][j] * scale + g_bh[idx];
        }
}

__global__ __launch_bounds__(256) void k_softmax() {
    float* row = g_S + (size_t)blockIdx.x * L_DIM;
    int t = threadIdx.x;
    int lane = t & 31, warp = t >> 5;
    __shared__ float red[8];
    __shared__ float bval;
    float v[4];
#pragma unroll
    for (int i = 0; i < 4; i++) v[i] = row[t + 256 * i];
    float m = fmaxf(fmaxf(v[0], v[1]), fmaxf(v[2], v[3]));
#pragma unroll
    for (int o = 16; o; o >>= 1) m = fmaxf(m, __shfl_xor_sync(0xffffffffu, m, o));
    if (lane == 0) red[warp] = m;
    __syncthreads();
    if (t == 0) {
        float mm = red[0];
        for (int i = 1; i < 8; i++) mm = fmaxf(mm, red[i]);
        bval = mm;
    }
    __syncthreads();
    float mx = bval;
    float sum = 0;
#pragma unroll
    for (int i = 0; i < 4; i++) { v[i] = expf(v[i] - mx); sum += v[i]; }
#pragma unroll
    for (int o = 16; o; o >>= 1) sum += __shfl_xor_sync(0xffffffffu, sum, o);
    __syncthreads();
    if (lane == 0) red[warp] = sum;
    __syncthreads();
    if (t == 0) {
        float tot = 0;
        for (int i = 0; i < 8; i++) tot += red[i];
        bval = 1.0f / tot;
    }
    __syncthreads();
    float inv = bval;
#pragma unroll
    for (int i = 0; i < 4; i++) row[t + 256 * i] = v[i] * inv;
}

__global__ __launch_bounds__(256) void attn_av() {
    int h = blockIdx.y, l0 = blockIdx.x * 64;
    __shared__ float Ss[64][65];
    __shared__ float Vs[64][48];
    int tl = (threadIdx.x >> 4) << 2;
    int tc = (threadIdx.x & 15) * 3;
    float acc[4][3] = {};
    size_t sbase = (size_t)h * L_DIM * L_DIM;
    for (int m0 = 0; m0 < L_DIM; m0 += 64) {
        for (int i = threadIdx.x; i < 64 * 64; i += 256) {
            int r = i >> 6, c = i & 63;
            Ss[r][c] = g_S[sbase + (size_t)(l0 + r) * L_DIM + m0 + c];
        }
        for (int i = threadIdx.x; i < 64 * 48; i += 256) {
            int r = i / 48, c = i % 48;
            Vs[r][c] = g_qkv[(size_t)(m0 + r) * 2304 + h * 144 + 96 + c];
        }
        __syncthreads();
#pragma unroll 4
        for (int m = 0; m < 64; m++) {
            float s0 = Ss[tl][m], s1 = Ss[tl + 1][m], s2 = Ss[tl + 2][m], s3 = Ss[tl + 3][m];
            float w0 = Vs[m][tc], w1 = Vs[m][tc + 1], w2 = Vs[m][tc + 2];
            acc[0][0] += s0 * w0; acc[0][1] += s0 * w1; acc[0][2] += s0 * w2;
            acc[1][0] += s1 * w0; acc[1][1] += s1 * w1; acc[1][2] += s1 * w2;
            acc[2][0] += s2 * w0; acc[2][1] += s2 * w1; acc[2][2] += s2 * w2;
            acc[3][0] += s3 * w0; acc[3][1] += s3 * w1; acc[3][2] += s3 * w2;
        }
        __syncthreads();
    }
#pragma unroll
    for (int i = 0; i < 4; i++)
#pragma unroll
        for (int j = 0; j < 3; j++)
            g_y[(size_t)(l0 + tl + i) * E_DIM + h * HD_DIM + tc + j] = acc[i][j];
}

// ---------------- driver ----------------------------------------------------
extern "C" void kernel_launch(void* const* d_in, const int* in_sizes, int n_in,
                              void* d_out, int out_size) {
    const float* z        = (const float*)d_in[0];
    const float* t        = (const float*)d_in[1];
    const float* bias     = (const float*)d_in[2];
    const float* p2s_g    = (const float*)d_in[3];
    const float* p2s_b    = (const float*)d_in[4];
    const float* p2s_w    = (const float*)d_in[5];
    const float* t0_w     = (const float*)d_in[6];
    const float* t0_b     = (const float*)d_in[7];
    const float* t2_w     = (const float*)d_in[8];
    const float* t2_b     = (const float*)d_in[9];
    const float* proj_w   = (const float*)d_in[10];
    const float* o_w      = (const float*)d_in[11];
    const float* o_b      = (const float*)d_in[12];
    const float* ada_w    = (const float*)d_in[13];
    const float* ada_b    = (const float*)d_in[14];
    const float* fc1_w    = (const float*)d_in[15];
    const float* fc1_b    = (const float*)d_in[16];
    const float* fc2_w    = (const float*)d_in[17];
    const float* fc2_b    = (const float*)d_in[18];
    const float* fin_aw   = (const float*)d_in[19];
    const float* fin_ab   = (const float*)d_in[20];
    const float* fin_w    = (const float*)d_in[21];
    const float* fin_b    = (const float*)d_in[22];
    float* out = (float*)d_out;

    float *px, *ph, *pqkv, *py, *pt1, *pada;
    cudaGetSymbolAddress((void**)&px, g_x);
    cudaGetSymbolAddress((void**)&ph, g_h);
    cudaGetSymbolAddress((void**)&pqkv, g_qkv);
    cudaGetSymbolAddress((void**)&py, g_y);
    cudaGetSymbolAddress((void**)&pt1, g_t1);
    cudaGetSymbolAddress((void**)&pada, g_ada);

    k_copy<<<(L_DIM * E_DIM + 255) / 256, 256>>>(z, px, L_DIM * E_DIM);
    k_time1<<<3, 256>>>(t, t0_w, t0_b);
    k_time2<<<3, 256>>>(t2_w, t2_b);
    k_ada<<<(DEPTH * 6 * E_DIM + 2 * E_DIM + 255) / 256, 256>>>(ada_w, ada_b, fin_aw, fin_ab);
    k_bh<<<L_DIM * L_DIM / 8, 256>>>(bias, p2s_g, p2s_b, p2s_w);

    for (int d = 0; d < DEPTH; d++) {
        int ao = d * 6 * E_DIM;
        // h = mod(LN(x), sh1, sc1)
        k_lnmod<<<L_DIM, 256>>>(px, ao);
        // qkv = h @ pw^T
        gemm_nt<0><<<dim3(36, 16), 256>>>(ph, proj_w + (size_t)d * 3 * E_DIM * E_DIM, nullptr,
                                          nullptr, nullptr, pqkv, L_DIM, 3 * E_DIM, E_DIM, E_DIM);
        // scores + bias, softmax, AV
        attn_scores<<<dim3(16, 16, 16), 256>>>();
        k_softmax<<<H_DIM * L_DIM, 256>>>();
        attn_av<<<dim3(16, H_DIM), 256>>>();
        // x += g1 * (y @ ow^T + ob)   — residual fused in epilogue, writes g_x
        gemm_nt<0><<<dim3(12, 16), 256>>>(py, o_w + (size_t)d * E_DIM * E_DIM, o_b + d * E_DIM,
                                          px, pada + ao + 2 * E_DIM, px, L_DIM, E_DIM, E_DIM, E_DIM);
        // h2 = mod(LN(x), sh2, sc2)
        k_lnmod<<<L_DIM, 256>>>(px, ao + 3 * E_DIM);
        // t1 = gelu(h2 @ f1w^T + f1b)  — gelu fused in epilogue
        gemm_nt<1><<<dim3(48, 16), 256>>>(ph, fc1_w + (size_t)d * MLP_DIM * E_DIM, fc1_b + d * MLP_DIM,
                                          nullptr, nullptr, pt1, L_DIM, MLP_DIM, E_DIM, E_DIM);
        // x += g2 * (t1 @ f2w^T + f2b)
        gemm_nt<0><<<dim3(12, 16), 256>>>(pt1, fc2_w + (size_t)d * E_DIM * MLP_DIM, fc2_b + d * E_DIM,
                                          px, pada + ao + 5 * E_DIM, px, L_DIM, E_DIM, MLP_DIM, MLP_DIM);
    }
    // final: out = mod(LN(x), sh, sc) @ fin_w^T + fin_b
    k_lnmod<<<L_DIM, 256>>>(px, DEPTH * 6 * E_DIM);
    gemm_nt<0><<<dim3(12, 16), 256>>>(ph, fin_w, fin_b, nullptr, nullptr, out,
                                      L_DIM, E_DIM, E_DIM, E_DIM);
    (void)in_sizes; (void)n_in; (void)out_size;
}

// round 4
// speedup vs baseline: 1.0005x; 1.0005x over previous
#include <cuda_runtime.h>
#include <math.h>
#include <stdio.h>

#define L_DIM 1024
#define E_DIM 768
#define P_DIM 128
#define H_DIM 16
#define HD_DIM 48
#define DEPTH 8
#define MLP_DIM 3072
#define FREQ 256

// ---------------- scratch (device globals; no allocation allowed) ----------
__device__ float g_x[L_DIM * E_DIM];
__device__ float g_h[L_DIM * E_DIM];
__device__ float g_qkv[L_DIM * 3 * E_DIM];
__device__ float g_y[L_DIM * E_DIM];
__device__ float g_t1[L_DIM * MLP_DIM];
__device__ float g_S[(size_t)H_DIM * L_DIM * L_DIM];   // 64 MB scores/probs
__device__ float g_bh[(size_t)H_DIM * L_DIM * L_DIM];  // 64 MB attention bias
__device__ float g_hidden[E_DIM];
__device__ float g_cs[E_DIM];
__device__ float g_ada[DEPTH * 6 * E_DIM + 2 * E_DIM];

// ---------------- small kernels --------------------------------------------
__global__ void k_copy(const float* __restrict__ src, float* __restrict__ dst, int n) {
    int i = blockIdx.x * blockDim.x + threadIdx.x;
    if (i < n) dst[i] = src[i];
}

__device__ __forceinline__ float silu_f(float x) { return x / (1.0f + expf(-x)); }
__device__ __forceinline__ float gelu_f(float v) {
    float c = v + 0.044715f * v * v * v;
    return 0.5f * v * (1.0f + tanhf(0.7978845608028654f * c));
}

__global__ void k_time1(const float* __restrict__ t,
                        const float* __restrict__ w,   // (E, 256)
                        const float* __restrict__ b) {
    int i = blockIdx.x * blockDim.x + threadIdx.x;
    if (i >= E_DIM) return;
    float tv = t[0];
    float acc = 0.0f;
    const float kfac = -9.210340371976184f / 128.0f;  // -log(10000)/half
    for (int j = 0; j < 128; j++) {
        float f = expf(kfac * (float)j);
        float a = tv * f;
        acc += cosf(a) * w[i * 256 + j] + sinf(a) * w[i * 256 + 128 + j];
    }
    float h = acc + b[i];
    g_hidden[i] = silu_f(h);
}

__global__ void k_time2(const float* __restrict__ w,  // (E, E)
                        const float* __restrict__ b) {
    int i = blockIdx.x * blockDim.x + threadIdx.x;
    if (i >= E_DIM) return;
    float acc = 0.0f;
    for (int j = 0; j < E_DIM; j++) acc += g_hidden[j] * w[i * E_DIM + j];
    g_cs[i] = silu_f(acc + b[i]);
}

// ada for all 8 blocks + final, computed once
__global__ __launch_bounds__(256) void k_ada(const float* __restrict__ aw,   // (D,6E,E)
                                             const float* __restrict__ ab,   // (D,6E)
                                             const float* __restrict__ fw,   // (2E,E)
                                             const float* __restrict__ fb) { // (2E)
    __shared__ float scs[E_DIM];
    for (int i = threadIdx.x; i < E_DIM; i += 256) scs[i] = g_cs[i];
    __syncthreads();
    int o = blockIdx.x * 256 + threadIdx.x;
    const int NB = DEPTH * 6 * E_DIM;  // 36864
    if (o >= NB + 2 * E_DIM) return;
    const float* w;
    float bias;
    if (o < NB) {
        w = aw + (size_t)o * E_DIM;
        bias = ab[o];
    } else {
        int j = o - NB;
        w = fw + (size_t)j * E_DIM;
        bias = fb[j];
    }
    float acc = 0.0f;
    for (int j = 0; j < E_DIM; j++) acc += scs[j] * w[j];
    g_ada[o] = acc + bias;
}

// bh[h,l,m] = (LN(bias[l,m,:])*g+beta) dot p2s_w[h,:]
__global__ __launch_bounds__(256) void k_bh(const float* __restrict__ bias,
                                            const float* __restrict__ gam,
                                            const float* __restrict__ bet,
                                            const float* __restrict__ pw) {
    __shared__ float sw[H_DIM][P_DIM];
    __shared__ float sg[P_DIM], sb[P_DIM];
    for (int i = threadIdx.x; i < H_DIM * P_DIM; i += 256) sw[i >> 7][i & 127] = pw[i];
    if (threadIdx.x < P_DIM) { sg[threadIdx.x] = gam[threadIdx.x]; sb[threadIdx.x] = bet[threadIdx.x]; }
    __syncthreads();
    int warp = threadIdx.x >> 5, lane = threadIdx.x & 31;
    size_t idx = (size_t)blockIdx.x * 8 + warp;  // l*L + m
    const float* src = bias + idx * P_DIM;
    float v[4];
#pragma unroll
    for (int i = 0; i < 4; i++) v[i] = src[lane + 32 * i];
    float s = v[0] + v[1] + v[2] + v[3];
#pragma unroll
    for (int o = 16; o; o >>= 1) s += __shfl_xor_sync(0xffffffffu, s, o);
    float mean = s * (1.0f / 128.0f);
    float q = 0.0f;
#pragma unroll
    for (int i = 0; i < 4; i++) { float d = v[i] - mean; q += d * d; }
#pragma unroll
    for (int o = 16; o; o >>= 1) q += __shfl_xor_sync(0xffffffffu, q, o);
    float rs = rsqrtf(q * (1.0f / 128.0f) + 1e-6f);
    float n[4];
#pragma unroll
    for (int i = 0; i < 4; i++) {
        int p = lane + 32 * i;
        n[i] = (v[i] - mean) * rs * sg[p] + sb[p];
    }
#pragma unroll
    for (int h = 0; h < H_DIM; h++) {
        float a = n[0] * sw[h][lane] + n[1] * sw[h][lane + 32] +
                  n[2] * sw[h][lane + 64] + n[3] * sw[h][lane + 96];
#pragma unroll
        for (int o = 16; o; o >>= 1) a += __shfl_xor_sync(0xffffffffu, a, o);
        if (lane == 0) g_bh[(size_t)h * L_DIM * L_DIM + idx] = a;
    }
}

// LN(x) modulated -> g_h.  sh = g_ada[ada_off..], sc = g_ada[ada_off+E..]
__global__ __launch_bounds__(256) void k_lnmod(const float* __restrict__ x, int ada_off) {
    int l = blockIdx.x;
    int t = threadIdx.x;
    const float* row = x + (size_t)l * E_DIM;
    float v0 = row[t], v1 = row[t + 256], v2 = row[t + 512];
    __shared__ float red[8];
    __shared__ float smean, srs;
    int lane = t & 31, warp = t >> 5;
    float s = v0 + v1 + v2;
#pragma unroll
    for (int o = 16; o; o >>= 1) s += __shfl_xor_sync(0xffffffffu, s, o);
    if (lane == 0) red[warp] = s;
    __syncthreads();
    if (t == 0) {
        float tot = 0;
        for (int i = 0; i < 8; i++) tot += red[i];
        smean = tot * (1.0f / 768.0f);
    }
    __syncthreads();
    float mean = smean;
    float d0 = v0 - mean, d1 = v1 - mean, d2 = v2 - mean;
    float q = d0 * d0 + d1 * d1 + d2 * d2;
#pragma unroll
    for (int o = 16; o; o >>= 1) q += __shfl_xor_sync(0xffffffffu, q, o);
    __syncthreads();
    if (lane == 0) red[warp] = q;
    __syncthreads();
    if (t == 0) {
        float tot = 0;
        for (int i = 0; i < 8; i++) tot += red[i];
        srs = rsqrtf(tot * (1.0f / 768.0f) + 1e-6f);
    }
    __syncthreads();
    float rs = srs;
    const float* sh = g_ada + ada_off;
    const float* sc = g_ada + ada_off + E_DIM;
    float* out = g_h + (size_t)l * E_DIM;
    out[t]       = d0 * rs * (1.0f + sc[t])       + sh[t];
    out[t + 256] = d1 * rs * (1.0f + sc[t + 256]) + sh[t + 256];
    out[t + 512] = d2 * rs * (1.0f + sc[t + 512]) + sh[t + 512];
}

// ---------------- GEMM: C[M,N] = A[M,K] @ W[N,K]^T (+bias, act, residual) --
// ACT: 0 = none, 1 = gelu
// If res != nullptr: C[idx] = res[idx] + gate[col] * val   (residual-gated)
template <int ACT>
__global__ __launch_bounds__(256) void gemm_nt(const float* __restrict__ A,
                                               const float* __restrict__ W,
                                               const float* __restrict__ bias,
                                               const float* __restrict__ res,
                                               const float* __restrict__ gate,
                                               float* __restrict__ C,
                                               int M, int N, int K, int lda) {
    __shared__ float As[16][68];
    __shared__ float Ws[16][68];
    int bm = blockIdx.y * 64, bn = blockIdx.x * 64;
    int tid = threadIdx.x;
    int tm = (tid >> 4) << 2, tn = (tid & 15) << 2;
    int lm = tid >> 2;
    int lk = (tid & 3) << 2;
    float acc[4][4] = {};
    for (int k0 = 0; k0 < K; k0 += 16) {
        float4 av = *(const float4*)&A[(size_t)(bm + lm) * lda + k0 + lk];
        float4 wv = *(const float4*)&W[(size_t)(bn + lm) * K + k0 + lk];
        As[lk + 0][lm] = av.x; As[lk + 1][lm] = av.y; As[lk + 2][lm] = av.z; As[lk + 3][lm] = av.w;
        Ws[lk + 0][lm] = wv.x; Ws[lk + 1][lm] = wv.y; Ws[lk + 2][lm] = wv.z; Ws[lk + 3][lm] = wv.w;
        __syncthreads();
#pragma unroll
        for (int k = 0; k < 16; k++) {
            float4 a = *(const float4*)&As[k][tm];
            float4 b = *(const float4*)&Ws[k][tn];
            acc[0][0] += a.x * b.x; acc[0][1] += a.x * b.y; acc[0][2] += a.x * b.z; acc[0][3] += a.x * b.w;
            acc[1][0] += a.y * b.x; acc[1][1] += a.y * b.y; acc[1][2] += a.y * b.z; acc[1][3] += a.y * b.w;
            acc[2][0] += a.z * b.x; acc[2][1] += a.z * b.y; acc[2][2] += a.z * b.z; acc[2][3] += a.z * b.w;
            acc[3][0] += a.w * b.x; acc[3][1] += a.w * b.y; acc[3][2] += a.w * b.z; acc[3][3] += a.w * b.w;
        }
        __syncthreads();
    }
    float b4[4] = {0, 0, 0, 0};
    if (bias) {
#pragma unroll
        for (int j = 0; j < 4; j++) b4[j] = bias[bn + tn + j];
    }
    float gt[4] = {0, 0, 0, 0};
    if (res) {
#pragma unroll
        for (int j = 0; j < 4; j++) gt[j] = gate[bn + tn + j];
    }
#pragma unroll
    for (int i = 0; i < 4; i++) {
        size_t off = (size_t)(bm + tm + i) * N + bn + tn;
        float* cr = C + off;
#pragma unroll
        for (int j = 0; j < 4; j++) {
            float v = acc[i][j] + b4[j];
            if (ACT == 1) v = gelu_f(v);
            if (res) v = res[off + j] + gt[j] * v;
            cr[j] = v;
        }
    }
}

// ---------------- attention ------------------------------------------------
__global__ __launch_bounds__(256) void attn_scores() {
    const float scale = 0.14433756729740643f;  // 48^-0.5
    int h = blockIdx.z;
    int l0 = blockIdx.y * 64, m0 = blockIdx.x * 64;
    __shared__ float Qs[HD_DIM][65];
    __shared__ float Ks[HD_DIM][65];
    for (int i = threadIdx.x; i < 64 * 48; i += 256) {
        int r = i / 48, c = i % 48;
        Qs[c][r] = g_qkv[(size_t)(l0 + r) * 2304 + h * 144 + c];
        Ks[c][r] = g_qkv[(size_t)(m0 + r) * 2304 + h * 144 + 48 + c];
    }
    __syncthreads();
    int tl = (threadIdx.x >> 4) << 2, tm = (threadIdx.x & 15) << 2;
    float acc[4][4] = {};
#pragma unroll 4
    for (int c = 0; c < 48; c++) {
        float q0 = Qs[c][tl], q1 = Qs[c][tl + 1], q2 = Qs[c][tl + 2], q3 = Qs[c][tl + 3];
        float k0 = Ks[c][tm], k1 = Ks[c][tm + 1], k2 = Ks[c][tm + 2], k3 = Ks[c][tm + 3];
        acc[0][0] += q0 * k0; acc[0][1] += q0 * k1; acc[0][2] += q0 * k2; acc[0][3] += q0 * k3;
        acc[1][0] += q1 * k0; acc[1][1] += q1 * k1; acc[1][2] += q1 * k2; acc[1][3] += q1 * k3;
        acc[2][0] += q2 * k0; acc[2][1] += q2 * k1; acc[2][2] += q2 * k2; acc[2][3] += q2 * k3;
        acc[3][0] += q3 * k0; acc[3][1] += q3 * k1; acc[3][2] += q3 * k2; acc[3][3] += q3 * k3;
    }
    size_t base = (size_t)h * L_DIM * L_DIM;
#pragma unroll
    for (int i = 0; i < 4; i++)
#pragma unroll
        for (int j = 0; j < 4; j++) {
            size_t idx = base + (size_t)(l0 + tl + i) * L_DIM + m0 + tm + j;
            g_S[idx] = acc[i][j] * scale + g_bh[idx];
        }
}

__global__ __launch_bounds__(256) void k_softmax() {
    float* row = g_S + (size_t)blockIdx.x * L_DIM;
    int t = threadIdx.x;
    int lane = t & 31, warp = t >> 5;
    __shared__ float red[8];
    __shared__ float bval;
    float v[4];
#pragma unroll
    for (int i = 0; i < 4; i++) v[i] = row[t + 256 * i];
    float m = fmaxf(fmaxf(v[0], v[1]), fmaxf(v[2], v[3]));
#pragma unroll
    for (int o = 16; o; o >>= 1) m = fmaxf(m, __shfl_xor_sync(0xffffffffu, m, o));
    if (lane == 0) red[warp] = m;
    __syncthreads();
    if (t == 0) {
        float mm = red[0];
        for (int i = 1; i < 8; i++) mm = fmaxf(mm, red[i]);
        bval = mm;
    }
    __syncthreads();
    float mx = bval;
    float sum = 0;
#pragma unroll
    for (int i = 0; i < 4; i++) { v[i] = expf(v[i] - mx); sum += v[i]; }
#pragma unroll
    for (int o = 16; o; o >>= 1) sum += __shfl_xor_sync(0xffffffffu, sum, o);
    __syncthreads();
    if (lane == 0) red[warp] = sum;
    __syncthreads();
    if (t == 0) {
        float tot = 0;
        for (int i = 0; i < 8; i++) tot += red[i];
        bval = 1.0f / tot;
    }
    __syncthreads();
    float inv = bval;
#pragma unroll
    for (int i = 0; i < 4; i++) row[t + 256 * i] = v[i] * inv;
}

__global__ __launch_bounds__(256) void attn_av() {
    int h = blockIdx.y, l0 = blockIdx.x * 64;
    __shared__ float Ss[64][65];
    __shared__ float Vs[64][48];
    int tl = (threadIdx.x >> 4) << 2;
    int tc = (threadIdx.x & 15) * 3;
    float acc[4][3] = {};
    size_t sbase = (size_t)h * L_DIM * L_DIM;
    for (int m0 = 0; m0 < L_DIM; m0 += 64) {
        for (int i = threadIdx.x; i < 64 * 64; i += 256) {
            int r = i >> 6, c = i & 63;
            Ss[r][c] = g_S[sbase + (size_t)(l0 + r) * L_DIM + m0 + c];
        }
        for (int i = threadIdx.x; i < 64 * 48; i += 256) {
            int r = i / 48, c = i % 48;
            Vs[r][c] = g_qkv[(size_t)(m0 + r) * 2304 + h * 144 + 96 + c];
        }
        __syncthreads();
#pragma unroll 4
        for (int m = 0; m < 64; m++) {
            float s0 = Ss[tl][m], s1 = Ss[tl + 1][m], s2 = Ss[tl + 2][m], s3 = Ss[tl + 3][m];
            float w0 = Vs[m][tc], w1 = Vs[m][tc + 1], w2 = Vs[m][tc + 2];
            acc[0][0] += s0 * w0; acc[0][1] += s0 * w1; acc[0][2] += s0 * w2;
            acc[1][0] += s1 * w0; acc[1][1] += s1 * w1; acc[1][2] += s1 * w2;
            acc[2][0] += s2 * w0; acc[2][1] += s2 * w1; acc[2][2] += s2 * w2;
            acc[3][0] += s3 * w0; acc[3][1] += s3 * w1; acc[3][2] += s3 * w2;
        }
        __syncthreads();
    }
#pragma unroll
    for (int i = 0; i < 4; i++)
#pragma unroll
        for (int j = 0; j < 3; j++)
            g_y[(size_t)(l0 + tl + i) * E_DIM + h * HD_DIM + tc + j] = acc[i][j];
}

// ---------------- driver ----------------------------------------------------
extern "C" void kernel_launch(void* const* d_in, const int* in_sizes, int n_in,
                              void* d_out, int out_size) {
    const float* z        = (const float*)d_in[0];
    const float* t        = (const float*)d_in[1];
    const float* bias     = (const float*)d_in[2];
    const float* p2s_g    = (const float*)d_in[3];
    const float* p2s_b    = (const float*)d_in[4];
    const float* p2s_w    = (const float*)d_in[5];
    const float* t0_w     = (const float*)d_in[6];
    const float* t0_b     = (const float*)d_in[7];
    const float* t2_w     = (const float*)d_in[8];
    const float* t2_b     = (const float*)d_in[9];
    const float* proj_w   = (const float*)d_in[10];
    const float* o_w      = (const float*)d_in[11];
    const float* o_b      = (const float*)d_in[12];
    const float* ada_w    = (const float*)d_in[13];
    const float* ada_b    = (const float*)d_in[14];
    const float* fc1_w    = (const float*)d_in[15];
    const float* fc1_b    = (const float*)d_in[16];
    const float* fc2_w    = (const float*)d_in[17];
    const float* fc2_b    = (const float*)d_in[18];
    const float* fin_aw   = (const float*)d_in[19];
    const float* fin_ab   = (const float*)d_in[20];
    const float* fin_w    = (const float*)d_in[21];
    const float* fin_b    = (const float*)d_in[22];
    float* out = (float*)d_out;

    float *px, *ph, *pqkv, *py, *pt1, *pada;
    cudaGetSymbolAddress((void**)&px, g_x);
    cudaGetSymbolAddress((void**)&ph, g_h);
    cudaGetSymbolAddress((void**)&pqkv, g_qkv);
    cudaGetSymbolAddress((void**)&py, g_y);
    cudaGetSymbolAddress((void**)&pt1, g_t1);
    cudaGetSymbolAddress((void**)&pada, g_ada);

    k_copy<<<(L_DIM * E_DIM + 255) / 256, 256>>>(z, px, L_DIM * E_DIM);
    k_time1<<<3, 256>>>(t, t0_w, t0_b);
    k_time2<<<3, 256>>>(t2_w, t2_b);
    k_ada<<<(DEPTH * 6 * E_DIM + 2 * E_DIM + 255) / 256, 256>>>(ada_w, ada_b, fin_aw, fin_ab);
    k_bh<<<L_DIM * L_DIM / 8, 256>>>(bias, p2s_g, p2s_b, p2s_w);

    for (int d = 0; d < DEPTH; d++) {
        int ao = d * 6 * E_DIM;
        // h = mod(LN(x), sh1, sc1)
        k_lnmod<<<L_DIM, 256>>>(px, ao);
        // qkv = h @ pw^T
        gemm_nt<0><<<dim3(36, 16), 256>>>(ph, proj_w + (size_t)d * 3 * E_DIM * E_DIM, nullptr,
                                          nullptr, nullptr, pqkv, L_DIM, 3 * E_DIM, E_DIM, E_DIM);
        // scores + bias, softmax, AV
        attn_scores<<<dim3(16, 16, 16), 256>>>();
        k_softmax<<<H_DIM * L_DIM, 256>>>();
        attn_av<<<dim3(16, H_DIM), 256>>>();
        // x += g1 * (y @ ow^T + ob)   — residual fused in epilogue, writes g_x
        gemm_nt<0><<<dim3(12, 16), 256>>>(py, o_w + (size_t)d * E_DIM * E_DIM, o_b + d * E_DIM,
                                          px, pada + ao + 2 * E_DIM, px, L_DIM, E_DIM, E_DIM, E_DIM);
        // h2 = mod(LN(x), sh2, sc2)
        k_lnmod<<<L_DIM, 256>>>(px, ao + 3 * E_DIM);
        // t1 = gelu(h2 @ f1w^T + f1b)  — gelu fused in epilogue
        gemm_nt<1><<<dim3(48, 16), 256>>>(ph, fc1_w + (size_t)d * MLP_DIM * E_DIM, fc1_b + d * MLP_DIM,
                                          nullptr, nullptr, pt1, L_DIM, MLP_DIM, E_DIM, E_DIM);
        // x += g2 * (t1 @ f2w^T + f2b)
        gemm_nt<0><<<dim3(12, 16), 256>>>(pt1, fc2_w + (size_t)d * E_DIM * MLP_DIM, fc2_b + d * E_DIM,
                                          px, pada + ao + 5 * E_DIM, px, L_DIM, E_DIM, MLP_DIM, MLP_DIM);
    }
    // final: out = mod(LN(x), sh, sc) @ fin_w^T + fin_b
    k_lnmod<<<L_DIM, 256>>>(px, DEPTH * 6 * E_DIM);
    gemm_nt<0><<<dim3(12, 16), 256>>>(ph, fin_w, fin_b, nullptr, nullptr, out,
                                      L_DIM, E_DIM, E_DIM, E_DIM);
    (void)in_sizes; (void)n_in; (void)out_size;
}

// round 8
// speedup vs baseline: 1.3762x; 1.3755x over previous
#include <cuda_runtime.h>
#include <cuda_bf16.h>
#include <cstdint>
#include <math.h>

#define L_DIM 1024
#define E_DIM 768
#define P_DIM 128
#define H_DIM 16
#define HD_DIM 48
#define DEPTH 8
#define MLP_DIM 3072

// ---------------- scratch (device globals) ---------------------------------
__device__ float g_x[L_DIM * E_DIM];
__device__ float g_qkv[L_DIM * 3 * E_DIM];
__device__ float g_y[L_DIM * E_DIM];
__device__ float g_S[(size_t)H_DIM * L_DIM * L_DIM];
__device__ float g_bh[(size_t)H_DIM * L_DIM * L_DIM];
__device__ float g_hidden[E_DIM];
__device__ float g_cs[E_DIM];
__device__ float g_ada[DEPTH * 6 * E_DIM + 2 * E_DIM];

// bf16 split-triple buffers (A-pattern: hi,lo,hi ; W-pattern: hi,hi,lo)
__device__ __align__(16) __nv_bfloat16 g_h3[L_DIM * 3 * E_DIM];
__device__ __align__(16) __nv_bfloat16 g_y3[L_DIM * 3 * E_DIM];
__device__ __align__(16) __nv_bfloat16 g_t13[(size_t)L_DIM * 3 * MLP_DIM];
// weights: proj | o | fc1 | fc2 | fin
#define OFF_PROJ 0ULL
#define OFF_O    42467328ULL
#define OFF_FC1  56623104ULL
#define OFF_FC2  113246208ULL
#define OFF_FIN  169869312ULL
#define W3_TOTAL 171638784ULL
__device__ __align__(16) __nv_bfloat16 g_w3[W3_TOTAL];

// ---------------- helpers ----------------------------------------------------
__device__ __forceinline__ uint32_t smem_u32(const void* p) {
    uint32_t a;
    asm("{ .reg .u64 t; cvta.to.shared.u64 t, %1; cvt.u32.u64 %0, t; }" : "=r"(a) : "l"(p));
    return a;
}
__device__ __forceinline__ uint32_t lds32(uint32_t a) {
    uint32_t v;
    asm volatile("ld.shared.b32 %0, [%1];" : "=r"(v) : "r"(a));
    return v;
}
__device__ __forceinline__ void mma16816(float* c, const uint32_t* a, uint32_t b0, uint32_t b1) {
    asm volatile(
        "mma.sync.aligned.m16n8k16.row.col.f32.bf16.bf16.f32 "
        "{%0,%1,%2,%3}, {%4,%5,%6,%7}, {%8,%9}, {%0,%1,%2,%3};"
        : "+f"(c[0]), "+f"(c[1]), "+f"(c[2]), "+f"(c[3])
        : "r"(a[0]), "r"(a[1]), "r"(a[2]), "r"(a[3]), "r"(b0), "r"(b1));
}
__device__ __forceinline__ void bf16split(float v, unsigned short& hi, unsigned short& lo) {
    __nv_bfloat16 h = __float2bfloat16(v);
    __nv_bfloat16 l = __float2bfloat16(v - __bfloat162float(h));
    hi = __bfloat16_as_ushort(h);
    lo = __bfloat16_as_ushort(l);
}
__device__ __forceinline__ uint32_t pk2(unsigned short a, unsigned short b) {
    return (uint32_t)a | ((uint32_t)b << 16);
}
__device__ __forceinline__ float gelu_f(float v) {
    float c = v + 0.044715f * v * v * v;
    return 0.5f * v * (1.0f + tanhf(0.7978845608028654f * c));
}
__device__ __forceinline__ float silu_f(float x) { return x / (1.0f + expf(-x)); }

// ---------------- fp32 -> split-triple bf16 conversion ----------------------
// WPAT=0: (hi,lo,hi)  [activations/A]   WPAT=1: (hi,hi,lo)  [weights/B]
template <int WPAT>
__global__ void k_cvt3(const float* __restrict__ src, __nv_bfloat16* __restrict__ dst, int n8) {
    int t = blockIdx.x * blockDim.x + threadIdx.x;
    if (t >= n8) return;
    const float4* s4 = (const float4*)src + (size_t)t * 2;
    float4 p = s4[0], q = s4[1];
    float v[8] = {p.x, p.y, p.z, p.w, q.x, q.y, q.z, q.w};
    unsigned short o[24];
#pragma unroll
    for (int e = 0; e < 8; e++) {
        unsigned short hi, lo;
        bf16split(v[e], hi, lo);
        if (WPAT) { o[3 * e] = hi; o[3 * e + 1] = hi; o[3 * e + 2] = lo; }
        else      { o[3 * e] = hi; o[3 * e + 1] = lo; o[3 * e + 2] = hi; }
    }
    uint4* d = (uint4*)((char*)dst + (size_t)t * 48);
    uint4 w;
    w.x = pk2(o[0], o[1]);   w.y = pk2(o[2], o[3]);   w.z = pk2(o[4], o[5]);   w.w = pk2(o[6], o[7]);
    d[0] = w;
    w.x = pk2(o[8], o[9]);   w.y = pk2(o[10], o[11]); w.z = pk2(o[12], o[13]); w.w = pk2(o[14], o[15]);
    d[1] = w;
    w.x = pk2(o[16], o[17]); w.y = pk2(o[18], o[19]); w.z = pk2(o[20], o[21]); w.w = pk2(o[22], o[23]);
    d[2] = w;
}

// ---------------- tensor-core GEMM ------------------------------------------
// C[M=1024, Ntot] = A3[M,K3] @ W3[Ntot,K3]^T  in bf16 split-triple (K3 = 3K)
// NT: N tile (128 or 64). M tile fixed 128. 256 threads.
// ACT: gelu on (acc+bias). RES: Cf = res + gate*val. O3: also write A-pattern bf16 triple.
template <int NT, int ACT, int RES, int O3>
__global__ void __launch_bounds__(256) gemm_bf16(
    const __nv_bfloat16* __restrict__ A3, const __nv_bfloat16* __restrict__ W3,
    const float* __restrict__ bias, const float* __restrict__ res,
    const float* __restrict__ gate, float* __restrict__ Cf,
    __nv_bfloat16* __restrict__ C3, int Ntot, int K3) {
    constexpr int SA_B = 80;                    // bytes per 32-half row (padded)
    constexpr int A_BYTES = 128 * SA_B;         // 10240
    constexpr int W_BYTES = NT * SA_B;
    constexpr int STAGE = A_BYTES + W_BYTES;
    constexpr int PIPE = 3;
    extern __shared__ char smem[];
    uint32_t sbase = smem_u32(smem);

    const int tid = threadIdx.x;
    const int wid = tid >> 5, lane = tid & 31;
    const int g = lane >> 2, tig = lane & 3;
    const int bm = blockIdx.y * 128, bn = blockIdx.x * NT;

    constexpr int WN_WARPS = (NT == 128) ? 4 : 2;
    constexpr int WM = (NT == 128) ? 64 : 32;
    constexpr int WN = 32;
    constexpr int MA = WM / 16;
    constexpr int NA = WN / 8;
    const int wm0 = (wid / WN_WARPS) * WM;
    const int wn0 = (wid % WN_WARPS) * WN;

    float acc[MA][NA][4] = {};
    const int S = K3 >> 5;

    auto issue_stage = [&](int s) {
        if (s < S) {
            int buf = s % PIPE;
            uint32_t sA = sbase + buf * STAGE;
            uint32_t sW = sA + A_BYTES;
            int k0 = s << 5;
#pragma unroll
            for (int t2 = 0; t2 < 2; t2++) {
                int chunk = tid + t2 * 256;
                int row = chunk >> 2, c4 = chunk & 3;
                const __nv_bfloat16* gp = A3 + (size_t)(bm + row) * K3 + k0 + c4 * 8;
                asm volatile("cp.async.cg.shared.global [%0], [%1], 16;" ::
                             "r"(sA + row * SA_B + c4 * 16), "l"(gp));
            }
#pragma unroll
            for (int t2 = 0; t2 < NT / 64; t2++) {
                int chunk = tid + t2 * 256;
                int row = chunk >> 2, c4 = chunk & 3;
                const __nv_bfloat16* gp = W3 + (size_t)(bn + row) * K3 + k0 + c4 * 8;
                asm volatile("cp.async.cg.shared.global [%0], [%1], 16;" ::
                             "r"(sW + row * SA_B + c4 * 16), "l"(gp));
            }
        }
        asm volatile("cp.async.commit_group;" ::: "memory");
    };

    issue_stage(0);
    issue_stage(1);

    for (int s = 0; s < S; s++) {
        asm volatile("cp.async.wait_group %0;" ::"n"(PIPE - 2) : "memory");
        __syncthreads();
        int buf = s % PIPE;
        uint32_t sA = sbase + buf * STAGE + wm0 * SA_B;
        uint32_t sW = sbase + buf * STAGE + A_BYTES + wn0 * SA_B;
#pragma unroll
        for (int kk = 0; kk < 2; kk++) {
            int kb = (kk * 16 + 2 * tig) * 2;  // byte offset of k within row
            uint32_t a[MA][4];
#pragma unroll
            for (int im = 0; im < MA; im++) {
                uint32_t r = sA + (im * 16 + g) * SA_B + kb;
                a[im][0] = lds32(r);
                a[im][1] = lds32(r + 8 * SA_B);
                a[im][2] = lds32(r + 16);
                a[im][3] = lds32(r + 8 * SA_B + 16);
            }
#pragma unroll
            for (int in2 = 0; in2 < NA; in2++) {
                uint32_t rb = sW + (in2 * 8 + g) * SA_B + kb;
                uint32_t b0 = lds32(rb), b1 = lds32(rb + 16);
#pragma unroll
                for (int im = 0; im < MA; im++) mma16816(acc[im][in2], a[im], b0, b1);
            }
        }
        issue_stage(s + PIPE - 1);
    }

    // epilogue
#pragma unroll
    for (int im = 0; im < MA; im++) {
#pragma unroll
        for (int in2 = 0; in2 < NA; in2++) {
            int r0 = bm + wm0 + im * 16 + g;
            int c0 = bn + wn0 + in2 * 8 + 2 * tig;
            float bv0 = bias ? bias[c0] : 0.0f;
            float bv1 = bias ? bias[c0 + 1] : 0.0f;
            float gv0 = 0.0f, gv1 = 0.0f;
            if (RES) { gv0 = gate[c0]; gv1 = gate[c0 + 1]; }
#pragma unroll
            for (int rh = 0; rh < 2; rh++) {
                int r = r0 + rh * 8;
                float v0 = acc[im][in2][rh * 2 + 0] + bv0;
                float v1 = acc[im][in2][rh * 2 + 1] + bv1;
                if (ACT) { v0 = gelu_f(v0); v1 = gelu_f(v1); }
                if (RES) {
                    v0 = res[(size_t)r * Ntot + c0] + gv0 * v0;
                    v1 = res[(size_t)r * Ntot + c0 + 1] + gv1 * v1;
                }
                if (Cf) {
                    Cf[(size_t)r * Ntot + c0] = v0;
                    Cf[(size_t)r * Ntot + c0 + 1] = v1;
                }
                if (O3) {
                    unsigned short h0, l0, h1, l1;
                    bf16split(v0, h0, l0);
                    bf16split(v1, h1, l1);
                    uint32_t* dp = (uint32_t*)(C3 + (size_t)r * 3 * Ntot + 3 * c0);
                    dp[0] = pk2(h0, l0);
                    dp[1] = pk2(h0, h1);
                    dp[2] = pk2(l1, h1);
                }
            }
        }
    }
}

// ---------------- small kernels ---------------------------------------------
__global__ void k_copy(const float* __restrict__ src, float* __restrict__ dst, int n) {
    int i = blockIdx.x * blockDim.x + threadIdx.x;
    if (i < n) dst[i] = src[i];
}

__global__ void k_time1(const float* __restrict__ t, const float* __restrict__ w,
                        const float* __restrict__ b) {
    int i = blockIdx.x * blockDim.x + threadIdx.x;
    if (i >= E_DIM) return;
    float tv = t[0];
    float acc = 0.0f;
    const float kfac = -9.210340371976184f / 128.0f;
    for (int j = 0; j < 128; j++) {
        float f = expf(kfac * (float)j);
        float a = tv * f;
        acc += cosf(a) * w[i * 256 + j] + sinf(a) * w[i * 256 + 128 + j];
    }
    g_hidden[i] = silu_f(acc + b[i]);
}

__global__ void k_time2(const float* __restrict__ w, const float* __restrict__ b) {
    int i = blockIdx.x * blockDim.x + threadIdx.x;
    if (i >= E_DIM) return;
    float acc = 0.0f;
    for (int j = 0; j < E_DIM; j++) acc += g_hidden[j] * w[i * E_DIM + j];
    g_cs[i] = silu_f(acc + b[i]);
}

__global__ __launch_bounds__(256) void k_ada(const float* __restrict__ aw,
                                             const float* __restrict__ ab,
                                             const float* __restrict__ fw,
                                             const float* __restrict__ fb) {
    __shared__ float4 scs[192];
    for (int i = threadIdx.x; i < 192; i += 256) scs[i] = ((const float4*)g_cs)[i];
    __syncthreads();
    int wid = threadIdx.x >> 5, lane = threadIdx.x & 31;
    int o = blockIdx.x * 8 + wid;
    const int NB = DEPTH * 6 * E_DIM;
    if (o >= NB + 2 * E_DIM) return;
    const float* w;
    float bias;
    if (o < NB) { w = aw + (size_t)o * E_DIM; bias = ab[o]; }
    else        { w = fw + (size_t)(o - NB) * E_DIM; bias = fb[o - NB]; }
    const float4* w4 = (const float4*)w;
    float acc = 0.0f;
    for (int j = lane; j < 192; j += 32) {
        float4 a = w4[j];
        float4 c = scs[j];
        acc += a.x * c.x + a.y * c.y + a.z * c.z + a.w * c.w;
    }
#pragma unroll
    for (int off = 16; off; off >>= 1) acc += __shfl_xor_sync(0xffffffffu, acc, off);
    if (lane == 0) g_ada[o] = acc + bias;
}

__global__ __launch_bounds__(256) void k_bh(const float* __restrict__ bias,
                                            const float* __restrict__ gam,
                                            const float* __restrict__ bet,
                                            const float* __restrict__ pw) {
    __shared__ float sw[H_DIM][P_DIM];
    __shared__ float sg[P_DIM], sb[P_DIM];
    for (int i = threadIdx.x; i < H_DIM * P_DIM; i += 256) sw[i >> 7][i & 127] = pw[i];
    if (threadIdx.x < P_DIM) { sg[threadIdx.x] = gam[threadIdx.x]; sb[threadIdx.x] = bet[threadIdx.x]; }
    __syncthreads();
    int warp = threadIdx.x >> 5, lane = threadIdx.x & 31;
    size_t idx = (size_t)blockIdx.x * 8 + warp;
    const float* src = bias + idx * P_DIM;
    float v[4];
#pragma unroll
    for (int i = 0; i < 4; i++) v[i] = src[lane + 32 * i];
    float s = v[0] + v[1] + v[2] + v[3];
#pragma unroll
    for (int o = 16; o; o >>= 1) s += __shfl_xor_sync(0xffffffffu, s, o);
    float mean = s * (1.0f / 128.0f);
    float q = 0.0f;
#pragma unroll
    for (int i = 0; i < 4; i++) { float d = v[i] - mean; q += d * d; }
#pragma unroll
    for (int o = 16; o; o >>= 1) q += __shfl_xor_sync(0xffffffffu, q, o);
    float rs = rsqrtf(q * (1.0f / 128.0f) + 1e-6f);
    float n[4];
#pragma unroll
    for (int i = 0; i < 4; i++) {
        int p = lane + 32 * i;
        n[i] = (v[i] - mean) * rs * sg[p] + sb[p];
    }
#pragma unroll
    for (int h = 0; h < H_DIM; h++) {
        float a = n[0] * sw[h][lane] + n[1] * sw[h][lane + 32] +
                  n[2] * sw[h][lane + 64] + n[3] * sw[h][lane + 96];
#pragma unroll
        for (int o = 16; o; o >>= 1) a += __shfl_xor_sync(0xffffffffu, a, o);
        if (lane == 0) g_bh[(size_t)h * L_DIM * L_DIM + idx] = a;
    }
}

// LN(x) modulated -> g_h3 (bf16 A-pattern triple)
__global__ __launch_bounds__(256) void k_lnmod(const float* __restrict__ x, int ada_off) {
    int l = blockIdx.x;
    int t = threadIdx.x;
    const float* row = x + (size_t)l * E_DIM;
    float v0 = row[t], v1 = row[t + 256], v2 = row[t + 512];
    __shared__ float red[8];
    __shared__ float smean, srs;
    int lane = t & 31, warp = t >> 5;
    float s = v0 + v1 + v2;
#pragma unroll
    for (int o = 16; o; o >>= 1) s += __shfl_xor_sync(0xffffffffu, s, o);
    if (lane == 0) red[warp] = s;
    __syncthreads();
    if (t == 0) {
        float tot = 0;
        for (int i = 0; i < 8; i++) tot += red[i];
        smean = tot * (1.0f / 768.0f);
    }
    __syncthreads();
    float mean = smean;
    float d0 = v0 - mean, d1 = v1 - mean, d2 = v2 - mean;
    float q = d0 * d0 + d1 * d1 + d2 * d2;
#pragma unroll
    for (int o = 16; o; o >>= 1) q += __shfl_xor_sync(0xffffffffu, q, o);
    __syncthreads();
    if (lane == 0) red[warp] = q;
    __syncthreads();
    if (t == 0) {
        float tot = 0;
        for (int i = 0; i < 8; i++) tot += red[i];
        srs = rsqrtf(tot * (1.0f / 768.0f) + 1e-6f);
    }
    __syncthreads();
    float rs = srs;
    const float* sh = g_ada + ada_off;
    const float* sc = g_ada + ada_off + E_DIM;
    __nv_bfloat16* out3 = g_h3 + (size_t)l * (3 * E_DIM);
#pragma unroll
    for (int i = 0; i < 3; i++) {
        int p = t + 256 * i;
        float d = (i == 0) ? d0 : (i == 1) ? d1 : d2;
        float v = d * rs * (1.0f + sc[p]) + sh[p];
        unsigned short hi, lo;
        bf16split(v, hi, lo);
        out3[3 * p]     = __ushort_as_bfloat16(hi);
        out3[3 * p + 1] = __ushort_as_bfloat16(lo);
        out3[3 * p + 2] = __ushort_as_bfloat16(hi);
    }
}

// ---------------- attention (fp32) ------------------------------------------
__global__ __launch_bounds__(256) void attn_scores() {
    const float scale = 0.14433756729740643f;
    int h = blockIdx.z;
    int l0 = blockIdx.y * 64, m0 = blockIdx.x * 64;
    __shared__ float Qs[HD_DIM][65];
    __shared__ float Ks[HD_DIM][65];
    for (int i = threadIdx.x; i < 64 * 48; i += 256) {
        int r = i / 48, c = i % 48;
        Qs[c][r] = g_qkv[(size_t)(l0 + r) * 2304 + h * 144 + c];
        Ks[c][r] = g_qkv[(size_t)(m0 + r) * 2304 + h * 144 + 48 + c];
    }
    __syncthreads();
    int tl = (threadIdx.x >> 4) << 2, tm = (threadIdx.x & 15) << 2;
    float acc[4][4] = {};
#pragma unroll 4
    for (int c = 0; c < 48; c++) {
        float q0 = Qs[c][tl], q1 = Qs[c][tl + 1], q2 = Qs[c][tl + 2], q3 = Qs[c][tl + 3];
        float k0 = Ks[c][tm], k1 = Ks[c][tm + 1], k2 = Ks[c][tm + 2], k3 = Ks[c][tm + 3];
        acc[0][0] += q0 * k0; acc[0][1] += q0 * k1; acc[0][2] += q0 * k2; acc[0][3] += q0 * k3;
        acc[1][0] += q1 * k0; acc[1][1] += q1 * k1; acc[1][2] += q1 * k2; acc[1][3] += q1 * k3;
        acc[2][0] += q2 * k0; acc[2][1] += q2 * k1; acc[2][2] += q2 * k2; acc[2][3] += q2 * k3;
        acc[3][0] += q3 * k0; acc[3][1] += q3 * k1; acc[3][2] += q3 * k2; acc[3][3] += q3 * k3;
    }
    size_t base = (size_t)h * L_DIM * L_DIM;
#pragma unroll
    for (int i = 0; i < 4; i++)
#pragma unroll
        for (int j = 0; j < 4; j++) {
            size_t idx = base + (size_t)(l0 + tl + i) * L_DIM + m0 + tm + j;
            g_S[idx] = acc[i][j] * scale + g_bh[idx];
        }
}

__global__ __launch_bounds__(256) void k_softmax() {
    float* row = g_S + (size_t)blockIdx.x * L_DIM;
    int t = threadIdx.x;
    int lane = t & 31, warp = t >> 5;
    __shared__ float red[8];
    __shared__ float bval;
    float v[4];
#pragma unroll
    for (int i = 0; i < 4; i++) v[i] = row[t + 256 * i];
    float m = fmaxf(fmaxf(v[0], v[1]), fmaxf(v[2], v[3]));
#pragma unroll
    for (int o = 16; o; o >>= 1) m = fmaxf(m, __shfl_xor_sync(0xffffffffu, m, o));
    if (lane == 0) red[warp] = m;
    __syncthreads();
    if (t == 0) {
        float mm = red[0];
        for (int i = 1; i < 8; i++) mm = fmaxf(mm, red[i]);
        bval = mm;
    }
    __syncthreads();
    float mx = bval;
    float sum = 0;
#pragma unroll
    for (int i = 0; i < 4; i++) { v[i] = expf(v[i] - mx); sum += v[i]; }
#pragma unroll
    for (int o = 16; o; o >>= 1) sum += __shfl_xor_sync(0xffffffffu, sum, o);
    __syncthreads();
    if (lane == 0) red[warp] = sum;
    __syncthreads();
    if (t == 0) {
        float tot = 0;
        for (int i = 0; i < 8; i++) tot += red[i];
        bval = 1.0f / tot;
    }
    __syncthreads();
    float inv = bval;
#pragma unroll
    for (int i = 0; i < 4; i++) row[t + 256 * i] = v[i] * inv;
}

__global__ __launch_bounds__(256) void attn_av() {
    int h = blockIdx.y, l0 = blockIdx.x * 64;
    __shared__ float Ss[64][65];
    __shared__ float Vs[64][48];
    int tl = (threadIdx.x >> 4) << 2;
    int tc = (threadIdx.x & 15) * 3;
    float acc[4][3] = {};
    size_t sbase = (size_t)h * L_DIM * L_DIM;
    for (int m0 = 0; m0 < L_DIM; m0 += 64) {
        for (int i = threadIdx.x; i < 64 * 64; i += 256) {
            int r = i >> 6, c = i & 63;
            Ss[r][c] = g_S[sbase + (size_t)(l0 + r) * L_DIM + m0 + c];
        }
        for (int i = threadIdx.x; i < 64 * 48; i += 256) {
            int r = i / 48, c = i % 48;
            Vs[r][c] = g_qkv[(size_t)(m0 + r) * 2304 + h * 144 + 96 + c];
        }
        __syncthreads();
#pragma unroll 4
        for (int m = 0; m < 64; m++) {
            float s0 = Ss[tl][m], s1 = Ss[tl + 1][m], s2 = Ss[tl + 2][m], s3 = Ss[tl + 3][m];
            float w0 = Vs[m][tc], w1 = Vs[m][tc + 1], w2 = Vs[m][tc + 2];
            acc[0][0] += s0 * w0; acc[0][1] += s0 * w1; acc[0][2] += s0 * w2;
            acc[1][0] += s1 * w0; acc[1][1] += s1 * w1; acc[1][2] += s1 * w2;
            acc[2][0] += s2 * w0; acc[2][1] += s2 * w1; acc[2][2] += s2 * w2;
            acc[3][0] += s3 * w0; acc[3][1] += s3 * w1; acc[3][2] += s3 * w2;
        }
        __syncthreads();
    }
#pragma unroll
    for (int i = 0; i < 4; i++)
#pragma unroll
        for (int j = 0; j < 3; j++)
            g_y[(size_t)(l0 + tl + i) * E_DIM + h * HD_DIM + tc + j] = acc[i][j];
}

// ---------------- driver ------------------------------------------------------
extern "C" void kernel_launch(void* const* d_in, const int* in_sizes, int n_in,
                              void* d_out, int out_size) {
    const float* z      = (const float*)d_in[0];
    const float* t      = (const float*)d_in[1];
    const float* bias   = (const float*)d_in[2];
    const float* p2s_g  = (const float*)d_in[3];
    const float* p2s_b  = (const float*)d_in[4];
    const float* p2s_w  = (const float*)d_in[5];
    const float* t0_w   = (const float*)d_in[6];
    const float* t0_b   = (const float*)d_in[7];
    const float* t2_w   = (const float*)d_in[8];
    const float* t2_b   = (const float*)d_in[9];
    const float* proj_w = (const float*)d_in[10];
    const float* o_w    = (const float*)d_in[11];
    const float* o_b    = (const float*)d_in[12];
    const float* ada_w  = (const float*)d_in[13];
    const float* ada_b  = (const float*)d_in[14];
    const float* fc1_w  = (const float*)d_in[15];
    const float* fc1_b  = (const float*)d_in[16];
    const float* fc2_w  = (const float*)d_in[17];
    const float* fc2_b  = (const float*)d_in[18];
    const float* fin_aw = (const float*)d_in[19];
    const float* fin_ab = (const float*)d_in[20];
    const float* fin_w  = (const float*)d_in[21];
    const float* fin_b  = (const float*)d_in[22];
    float* out = (float*)d_out;

    float *px, *pqkv, *py, *pada;
    __nv_bfloat16 *ph3, *py3, *pt13, *pw3;
    cudaGetSymbolAddress((void**)&px, g_x);
    cudaGetSymbolAddress((void**)&pqkv, g_qkv);
    cudaGetSymbolAddress((void**)&py, g_y);
    cudaGetSymbolAddress((void**)&pada, g_ada);
    cudaGetSymbolAddress((void**)&ph3, g_h3);
    cudaGetSymbolAddress((void**)&py3, g_y3);
    cudaGetSymbolAddress((void**)&pt13, g_t13);
    cudaGetSymbolAddress((void**)&pw3, g_w3);

    const int SM128 = 3 * (10240 + 10240);
    const int SM64  = 3 * (10240 + 5120);
    cudaFuncSetAttribute(gemm_bf16<128, 0, 0, 0>, cudaFuncAttributeMaxDynamicSharedMemorySize, SM128);
    cudaFuncSetAttribute(gemm_bf16<64, 0, 1, 0>, cudaFuncAttributeMaxDynamicSharedMemorySize, SM64);
    cudaFuncSetAttribute(gemm_bf16<64, 1, 0, 1>, cudaFuncAttributeMaxDynamicSharedMemorySize, SM64);
    cudaFuncSetAttribute(gemm_bf16<64, 0, 0, 0>, cudaFuncAttributeMaxDynamicSharedMemorySize, SM64);

    // ---- weight conversion (W-pattern: hi,hi,lo) ----
    {
        int n;
        n = 8 * 3 * E_DIM * E_DIM / 8;          // proj
        k_cvt3<1><<<(n + 255) / 256, 256>>>(proj_w, pw3 + OFF_PROJ, n);
        n = 8 * E_DIM * E_DIM / 8;              // o
        k_cvt3<1><<<(n + 255) / 256, 256>>>(o_w, pw3 + OFF_O, n);
        n = 8 * MLP_DIM * E_DIM / 8;            // fc1
        k_cvt3<1><<<(n + 255) / 256, 256>>>(fc1_w, pw3 + OFF_FC1, n);
        n = 8 * E_DIM * MLP_DIM / 8;            // fc2
        k_cvt3<1><<<(n + 255) / 256, 256>>>(fc2_w, pw3 + OFF_FC2, n);
        n = E_DIM * E_DIM / 8;                  // fin
        k_cvt3<1><<<(n + 255) / 256, 256>>>(fin_w, pw3 + OFF_FIN, n);
    }

    k_copy<<<(L_DIM * E_DIM + 255) / 256, 256>>>(z, px, L_DIM * E_DIM);
    k_time1<<<3, 256>>>(t, t0_w, t0_b);
    k_time2<<<3, 256>>>(t2_w, t2_b);
    k_ada<<<(DEPTH * 6 * E_DIM + 2 * E_DIM) / 8, 256>>>(ada_w, ada_b, fin_aw, fin_ab);
    k_bh<<<L_DIM * L_DIM / 8, 256>>>(bias, p2s_g, p2s_b, p2s_w);

    const int K3E = 3 * E_DIM;     // 2304
    const int K3M = 3 * MLP_DIM;   // 9216

    for (int d = 0; d < DEPTH; d++) {
        int ao = d * 6 * E_DIM;
        k_lnmod<<<L_DIM, 256>>>(px, ao);
        // qkv = h @ pw^T  (f32 out)
        gemm_bf16<128, 0, 0, 0><<<dim3(18, 8), 256, SM128>>>(
            ph3, pw3 + OFF_PROJ + (size_t)d * 3 * E_DIM * K3E, nullptr, nullptr, nullptr,
            pqkv, nullptr, 3 * E_DIM, K3E);
        attn_scores<<<dim3(16, 16, 16), 256>>>();
        k_softmax<<<H_DIM * L_DIM, 256>>>();
        attn_av<<<dim3(16, H_DIM), 256>>>();
        // y -> y3
        k_cvt3<0><<<(L_DIM * E_DIM / 8 + 255) / 256, 256>>>(py, py3, L_DIM * E_DIM / 8);
        // x += g1 * (y @ ow^T + ob)
        gemm_bf16<64, 0, 1, 0><<<dim3(12, 8), 256, SM64>>>(
            py3, pw3 + OFF_O + (size_t)d * E_DIM * K3E, o_b + d * E_DIM,
            px, pada + ao + 2 * E_DIM, px, nullptr, E_DIM, K3E);
        k_lnmod<<<L_DIM, 256>>>(px, ao + 3 * E_DIM);
        // t1_3 = split(gelu(h2 @ f1w^T + f1b))
        gemm_bf16<64, 1, 0, 1><<<dim3(48, 8), 256, SM64>>>(
            ph3, pw3 + OFF_FC1 + (size_t)d * MLP_DIM * K3E, fc1_b + d * MLP_DIM,
            nullptr, nullptr, nullptr, pt13, MLP_DIM, K3E);
        // x += g2 * (t1 @ f2w^T + f2b)
        gemm_bf16<64, 0, 1, 0><<<dim3(12, 8), 256, SM64>>>(
            pt13, pw3 + OFF_FC2 + (size_t)d * E_DIM * K3M, fc2_b + d * E_DIM,
            px, pada + ao + 5 * E_DIM, px, nullptr, E_DIM, K3M);
    }
    k_lnmod<<<L_DIM, 256>>>(px, DEPTH * 6 * E_DIM);
    gemm_bf16<64, 0, 0, 0><<<dim3(12, 8), 256, SM64>>>(
        ph3, pw3 + OFF_FIN, fin_b, nullptr, nullptr, out, nullptr, E_DIM, K3E);
    (void)in_sizes; (void)n_in; (void)out_size;
}

// round 13
// speedup vs baseline: 1.5531x; 1.1286x over previous
#include <cuda_runtime.h>
#include <cuda_fp16.h>
#include <cstdint>
#include <math.h>

#define L_DIM 1024
#define E_DIM 768
#define P_DIM 128
#define H_DIM 16
#define HD_DIM 48
#define DEPTH 8
#define MLP_DIM 3072

// ---------------- scratch (device globals) ---------------------------------
__device__ float g_x[L_DIM * E_DIM];
__device__ float g_qkv[L_DIM * 3 * E_DIM];
__device__ float g_S[(size_t)H_DIM * L_DIM * L_DIM];
__device__ float g_bh[(size_t)H_DIM * L_DIM * L_DIM];
__device__ float g_hidden[E_DIM];
__device__ float g_cs[E_DIM];
__device__ float g_ada[DEPTH * 6 * E_DIM + 2 * E_DIM];

// fp16 split-pair buffers (A-pattern: hi,lo ; W-pattern: hi,hi)
__device__ __align__(16) __half g_h2[L_DIM * 2 * E_DIM];
__device__ __align__(16) __half g_y2[L_DIM * 2 * E_DIM];
__device__ __align__(16) __half g_t12[(size_t)L_DIM * 2 * MLP_DIM];
// weights: proj | o | fc1 | fc2 | fin  (element counts in halves)
#define OFF_PROJ 0ULL
#define OFF_O    28311552ULL
#define OFF_FC1  37748736ULL
#define OFF_FC2  75497472ULL
#define OFF_FIN  113246208ULL
#define W2_TOTAL 114425856ULL
__device__ __align__(16) __half g_w2[W2_TOTAL];

// ---------------- helpers ----------------------------------------------------
__device__ __forceinline__ uint32_t smem_u32(const void* p) {
    uint32_t a;
    asm("{ .reg .u64 t; cvta.to.shared.u64 t, %1; cvt.u32.u64 %0, t; }" : "=r"(a) : "l"(p));
    return a;
}
__device__ __forceinline__ uint32_t lds32(uint32_t a) {
    uint32_t v;
    asm volatile("ld.shared.b32 %0, [%1];" : "=r"(v) : "r"(a));
    return v;
}
__device__ __forceinline__ void mma16816(float* c, const uint32_t* a, uint32_t b0, uint32_t b1) {
    asm volatile(
        "mma.sync.aligned.m16n8k16.row.col.f32.f16.f16.f32 "
        "{%0,%1,%2,%3}, {%4,%5,%6,%7}, {%8,%9}, {%0,%1,%2,%3};"
        : "+f"(c[0]), "+f"(c[1]), "+f"(c[2]), "+f"(c[3])
        : "r"(a[0]), "r"(a[1]), "r"(a[2]), "r"(a[3]), "r"(b0), "r"(b1));
}
__device__ __forceinline__ void f16split(float v, unsigned short& hi, unsigned short& lo) {
    __half h = __float2half_rn(v);
    __half l = __float2half_rn(v - __half2float(h));
    hi = __half_as_ushort(h);
    lo = __half_as_ushort(l);
}
__device__ __forceinline__ uint32_t pk2(unsigned short a, unsigned short b) {
    return (uint32_t)a | ((uint32_t)b << 16);
}
__device__ __forceinline__ float gelu_f(float v) {
    float c = v + 0.044715f * v * v * v;
    return 0.5f * v * (1.0f + tanhf(0.7978845608028654f * c));
}
__device__ __forceinline__ float silu_f(float x) { return x / (1.0f + expf(-x)); }

// ---------------- fp32 -> split-pair fp16 (W-pattern hi,hi) -----------------
__global__ void k_cvt2(const float* __restrict__ src, __half* __restrict__ dst, int n8) {
    int t = blockIdx.x * blockDim.x + threadIdx.x;
    if (t >= n8) return;
    const float4* s4 = (const float4*)src + (size_t)t * 2;
    float4 p = s4[0], q = s4[1];
    float v[8] = {p.x, p.y, p.z, p.w, q.x, q.y, q.z, q.w};
    uint32_t o[8];
#pragma unroll
    for (int e = 0; e < 8; e++) {
        unsigned short hi, lo;
        f16split(v[e], hi, lo);
        (void)lo;
        o[e] = pk2(hi, hi);
    }
    uint4* d = (uint4*)((char*)dst + (size_t)t * 32);
    d[0] = make_uint4(o[0], o[1], o[2], o[3]);
    d[1] = make_uint4(o[4], o[5], o[6], o[7]);
}

// ---------------- tensor-core GEMM (fp16 split-pair) ------------------------
// C[M=1024, Ntot] = A2[M,K2] @ W2[Ntot,K2]^T   (K2 = 2K)
template <int NT, int ACT, int RES, int O2>
__global__ void __launch_bounds__(256) gemm_fp16(
    const __half* __restrict__ A2, const __half* __restrict__ W2,
    const float* __restrict__ bias, const float* __restrict__ res,
    const float* __restrict__ gate, float* __restrict__ Cf,
    __half* __restrict__ C2, int Ntot, int K2) {
    constexpr int SA_B = 80;
    constexpr int A_BYTES = 128 * SA_B;
    constexpr int W_BYTES = NT * SA_B;
    constexpr int STAGE = A_BYTES + W_BYTES;
    constexpr int PIPE = 3;
    extern __shared__ char smem[];
    uint32_t sbase = smem_u32(smem);

    const int tid = threadIdx.x;
    const int wid = tid >> 5, lane = tid & 31;
    const int g = lane >> 2, tig = lane & 3;
    const int bm = blockIdx.y * 128, bn = blockIdx.x * NT;

    constexpr int WN_WARPS = (NT == 128) ? 4 : 2;
    constexpr int WM = (NT == 128) ? 64 : 32;
    constexpr int WN = 32;
    constexpr int MA = WM / 16;
    constexpr int NA = WN / 8;
    const int wm0 = (wid / WN_WARPS) * WM;
    const int wn0 = (wid % WN_WARPS) * WN;

    float acc[MA][NA][4] = {};
    const int S = K2 >> 5;

    auto issue_stage = [&](int s) {
        if (s < S) {
            int buf = s % PIPE;
            uint32_t sA = sbase + buf * STAGE;
            uint32_t sW = sA + A_BYTES;
            int k0 = s << 5;
#pragma unroll
            for (int t2 = 0; t2 < 2; t2++) {
                int chunk = tid + t2 * 256;
                int row = chunk >> 2, c4 = chunk & 3;
                const __half* gp = A2 + (size_t)(bm + row) * K2 + k0 + c4 * 8;
                asm volatile("cp.async.cg.shared.global [%0], [%1], 16;" ::
                             "r"(sA + row * SA_B + c4 * 16), "l"(gp));
            }
#pragma unroll
            for (int t2 = 0; t2 < NT / 64; t2++) {
                int chunk = tid + t2 * 256;
                int row = chunk >> 2, c4 = chunk & 3;
                const __half* gp = W2 + (size_t)(bn + row) * K2 + k0 + c4 * 8;
                asm volatile("cp.async.cg.shared.global [%0], [%1], 16;" ::
                             "r"(sW + row * SA_B + c4 * 16), "l"(gp));
            }
        }
        asm volatile("cp.async.commit_group;" ::: "memory");
    };

    issue_stage(0);
    issue_stage(1);

    for (int s = 0; s < S; s++) {
        asm volatile("cp.async.wait_group %0;" ::"n"(PIPE - 2) : "memory");
        __syncthreads();
        int buf = s % PIPE;
        uint32_t sA = sbase + buf * STAGE + wm0 * SA_B;
        uint32_t sW = sbase + buf * STAGE + A_BYTES + wn0 * SA_B;
#pragma unroll
        for (int kk = 0; kk < 2; kk++) {
            int kb = (kk * 16 + 2 * tig) * 2;
            uint32_t a[MA][4];
#pragma unroll
            for (int im = 0; im < MA; im++) {
                uint32_t r = sA + (im * 16 + g) * SA_B + kb;
                a[im][0] = lds32(r);
                a[im][1] = lds32(r + 8 * SA_B);
                a[im][2] = lds32(r + 16);
                a[im][3] = lds32(r + 8 * SA_B + 16);
            }
#pragma unroll
            for (int in2 = 0; in2 < NA; in2++) {
                uint32_t rb = sW + (in2 * 8 + g) * SA_B + kb;
                uint32_t b0 = lds32(rb), b1 = lds32(rb + 16);
#pragma unroll
                for (int im = 0; im < MA; im++) mma16816(acc[im][in2], a[im], b0, b1);
            }
        }
        issue_stage(s + PIPE - 1);
    }

#pragma unroll
    for (int im = 0; im < MA; im++) {
#pragma unroll
        for (int in2 = 0; in2 < NA; in2++) {
            int r0 = bm + wm0 + im * 16 + g;
            int c0 = bn + wn0 + in2 * 8 + 2 * tig;
            float bv0 = bias ? bias[c0] : 0.0f;
            float bv1 = bias ? bias[c0 + 1] : 0.0f;
            float gv0 = 0.0f, gv1 = 0.0f;
            if (RES) { gv0 = gate[c0]; gv1 = gate[c0 + 1]; }
#pragma unroll
            for (int rh = 0; rh < 2; rh++) {
                int r = r0 + rh * 8;
                float v0 = acc[im][in2][rh * 2 + 0] + bv0;
                float v1 = acc[im][in2][rh * 2 + 1] + bv1;
                if (ACT) { v0 = gelu_f(v0); v1 = gelu_f(v1); }
                if (RES) {
                    v0 = res[(size_t)r * Ntot + c0] + gv0 * v0;
                    v1 = res[(size_t)r * Ntot + c0 + 1] + gv1 * v1;
                }
                if (Cf) {
                    Cf[(size_t)r * Ntot + c0] = v0;
                    Cf[(size_t)r * Ntot + c0 + 1] = v1;
                }
                if (O2) {
                    unsigned short h0, l0, h1, l1;
                    f16split(v0, h0, l0);
                    f16split(v1, h1, l1);
                    uint32_t* dp = (uint32_t*)(C2 + (size_t)r * 2 * Ntot);
                    dp[c0] = pk2(h0, l0);
                    dp[c0 + 1] = pk2(h1, l1);
                }
            }
        }
    }
}

// ---------------- attention: scores via mma (fp16 3-term exact) -------------
// S[h, l, m] = (Q*scale)·K + bh.  CTA: 128 l x 128 m per head.
#define SCR_STRIDE 296   // 144 halves + 4 pad, bytes
#define SCR_SMEM (2 * 128 * SCR_STRIDE)
__global__ void __launch_bounds__(256) attn_scores_tc() {
    const float scale = 0.14433756729740643f;
    int h = blockIdx.z;
    int l0 = blockIdx.y * 128, m0 = blockIdx.x * 128;
    extern __shared__ char smem[];
    uint32_t sQ = smem_u32(smem);
    uint32_t sK = sQ + 128 * SCR_STRIDE;
    int tid = threadIdx.x;

    for (int i = tid; i < 128 * 48; i += 256) {
        int r = i / 48, c = i % 48;
        unsigned short hi, lo;
        float q = g_qkv[(size_t)(l0 + r) * 2304 + h * 144 + c] * scale;
        f16split(q, hi, lo);
        __half* qp = (__half*)(smem + r * SCR_STRIDE);
        qp[3 * c] = __ushort_as_half(hi);
        qp[3 * c + 1] = __ushort_as_half(lo);
        qp[3 * c + 2] = __ushort_as_half(hi);
        float k = g_qkv[(size_t)(m0 + r) * 2304 + h * 144 + 48 + c];
        f16split(k, hi, lo);
        __half* kp = (__half*)(smem + 128 * SCR_STRIDE + r * SCR_STRIDE);
        kp[3 * c] = __ushort_as_half(hi);
        kp[3 * c + 1] = __ushort_as_half(hi);
        kp[3 * c + 2] = __ushort_as_half(lo);
    }
    __syncthreads();

    int wid = tid >> 5, lane = tid & 31;
    int g = lane >> 2, tig = lane & 3;
    int wm0 = (wid >> 2) * 64, wn0 = (wid & 3) * 32;
    float acc[4][4][4] = {};
#pragma unroll
    for (int ks = 0; ks < 9; ks++) {
        int kb = (ks * 16 + 2 * tig) * 2;
        uint32_t a[4][4];
#pragma unroll
        for (int im = 0; im < 4; im++) {
            uint32_t r = sQ + (wm0 + im * 16 + g) * SCR_STRIDE + kb;
            a[im][0] = lds32(r);
            a[im][1] = lds32(r + 8 * SCR_STRIDE);
            a[im][2] = lds32(r + 16);
            a[im][3] = lds32(r + 8 * SCR_STRIDE + 16);
        }
#pragma unroll
        for (int in2 = 0; in2 < 4; in2++) {
            uint32_t rb = sK + (wn0 + in2 * 8 + g) * SCR_STRIDE + kb;
            uint32_t b0 = lds32(rb), b1 = lds32(rb + 16);
#pragma unroll
            for (int im = 0; im < 4; im++) mma16816(acc[im][in2], a[im], b0, b1);
        }
    }
    size_t base = (size_t)h * L_DIM * L_DIM;
#pragma unroll
    for (int im = 0; im < 4; im++) {
#pragma unroll
        for (int in2 = 0; in2 < 4; in2++) {
#pragma unroll
            for (int rh = 0; rh < 2; rh++) {
                int l = l0 + wm0 + im * 16 + g + rh * 8;
                int m = m0 + wn0 + in2 * 8 + 2 * tig;
                size_t idx = base + (size_t)l * L_DIM + m;
                g_S[idx] = acc[im][in2][rh * 2] + g_bh[idx];
                g_S[idx + 1] = acc[im][in2][rh * 2 + 1] + g_bh[idx + 1];
            }
        }
    }
}

// ---------------- attention: AV via mma (P dup x V pair) --------------------
// y2 pairs out. CTA: 128 l-rows x 48 cols per head. K2 per chunk = 256.
#define AV_STRIDE 528    // 256 halves + 8 pad, bytes (16B aligned)
#define AV_SMEM (128 * AV_STRIDE + 48 * AV_STRIDE)
__global__ void __launch_bounds__(128) attn_av_tc() {
    int h = blockIdx.y, l0 = blockIdx.x * 128;
    extern __shared__ char smem[];
    uint32_t sP = smem_u32(smem);
    uint32_t sV = sP + 128 * AV_STRIDE;
    int tid = threadIdx.x;
    int wid = tid >> 5, lane = tid & 31;
    int g = lane >> 2, tig = lane & 3;
    float acc[2][6][4] = {};
    size_t sbase = (size_t)h * L_DIM * L_DIM;

    for (int mc = 0; mc < L_DIM; mc += 128) {
        // P chunk: f32 -> fp16 dup (p,p)
        for (int i = tid; i < 128 * 32; i += 128) {
            int r = i >> 5, c4 = i & 31;
            float4 p = *(const float4*)&g_S[sbase + (size_t)(l0 + r) * L_DIM + mc + c4 * 4];
            unsigned short p0 = __half_as_ushort(__float2half_rn(p.x));
            unsigned short p1 = __half_as_ushort(__float2half_rn(p.y));
            unsigned short p2 = __half_as_ushort(__float2half_rn(p.z));
            unsigned short p3 = __half_as_ushort(__float2half_rn(p.w));
            *(uint4*)(smem + r * AV_STRIDE + c4 * 16) =
                make_uint4(pk2(p0, p0), pk2(p1, p1), pk2(p2, p2), pk2(p3, p3));
        }
        // V chunk transposed: rows c, cols m, (hi,lo) pairs
        for (int i = tid; i < 128 * 48; i += 128) {
            int m = i / 48, c = i % 48;
            float v = g_qkv[(size_t)(mc + m) * 2304 + h * 144 + 96 + c];
            unsigned short hi, lo;
            f16split(v, hi, lo);
            *(uint32_t*)(smem + 128 * AV_STRIDE + c * AV_STRIDE + m * 4) = pk2(hi, lo);
        }
        __syncthreads();
#pragma unroll
        for (int ks = 0; ks < 16; ks++) {
            int kb = (ks * 16 + 2 * tig) * 2;
            uint32_t a[2][4];
#pragma unroll
            for (int im = 0; im < 2; im++) {
                uint32_t r = sP + (wid * 32 + im * 16 + g) * AV_STRIDE + kb;
                a[im][0] = lds32(r);
                a[im][1] = lds32(r + 8 * AV_STRIDE);
                a[im][2] = lds32(r + 16);
                a[im][3] = lds32(r + 8 * AV_STRIDE + 16);
            }
#pragma unroll
            for (int in2 = 0; in2 < 6; in2++) {
                uint32_t rb = sV + (in2 * 8 + g) * AV_STRIDE + kb;
                uint32_t b0 = lds32(rb), b1 = lds32(rb + 16);
#pragma unroll
                for (int im = 0; im < 2; im++) mma16816(acc[im][in2], a[im], b0, b1);
            }
        }
        __syncthreads();
    }
#pragma unroll
    for (int im = 0; im < 2; im++) {
#pragma unroll
        for (int in2 = 0; in2 < 6; in2++) {
#pragma unroll
            for (int rh = 0; rh < 2; rh++) {
                int l = l0 + wid * 32 + im * 16 + g + rh * 8;
                int c0 = h * 48 + in2 * 8 + 2 * tig;
                float v0 = acc[im][in2][rh * 2];
                float v1 = acc[im][in2][rh * 2 + 1];
                unsigned short h0, lo0, h1, lo1;
                f16split(v0, h0, lo0);
                f16split(v1, h1, lo1);
                uint32_t* dp = (uint32_t*)(g_y2 + (size_t)l * 2 * E_DIM);
                dp[c0] = pk2(h0, lo0);
                dp[c0 + 1] = pk2(h1, lo1);
            }
        }
    }
}

// ---------------- small kernels ---------------------------------------------
__global__ void k_copy(const float* __restrict__ src, float* __restrict__ dst, int n) {
    int i = blockIdx.x * blockDim.x + threadIdx.x;
    if (i < n) dst[i] = src[i];
}

__global__ void k_time1(const float* __restrict__ t, const float* __restrict__ w,
                        const float* __restrict__ b) {
    int i = blockIdx.x * blockDim.x + threadIdx.x;
    if (i >= E_DIM) return;
    float tv = t[0];
    float acc = 0.0f;
    const float kfac = -9.210340371976184f / 128.0f;
    for (int j = 0; j < 128; j++) {
        float f = expf(kfac * (float)j);
        float a = tv * f;
        acc += cosf(a) * w[i * 256 + j] + sinf(a) * w[i * 256 + 128 + j];
    }
    g_hidden[i] = silu_f(acc + b[i]);
}

__global__ void k_time2(const float* __restrict__ w, const float* __restrict__ b) {
    int i = blockIdx.x * blockDim.x + threadIdx.x;
    if (i >= E_DIM) return;
    float acc = 0.0f;
    for (int j = 0; j < E_DIM; j++) acc += g_hidden[j] * w[i * E_DIM + j];
    g_cs[i] = silu_f(acc + b[i]);
}

__global__ __launch_bounds__(256) void k_ada(const float* __restrict__ aw,
                                             const float* __restrict__ ab,
                                             const float* __restrict__ fw,
                                             const float* __restrict__ fb) {
    __shared__ float4 scs[192];
    for (int i = threadIdx.x; i < 192; i += 256) scs[i] = ((const float4*)g_cs)[i];
    __syncthreads();
    int wid = threadIdx.x >> 5, lane = threadIdx.x & 31;
    int o = blockIdx.x * 8 + wid;
    const int NB = DEPTH * 6 * E_DIM;
    if (o >= NB + 2 * E_DIM) return;
    const float* w;
    float bias;
    if (o < NB) { w = aw + (size_t)o * E_DIM; bias = ab[o]; }
    else        { w = fw + (size_t)(o - NB) * E_DIM; bias = fb[o - NB]; }
    const float4* w4 = (const float4*)w;
    float acc = 0.0f;
    for (int j = lane; j < 192; j += 32) {
        float4 a = w4[j];
        float4 c = scs[j];
        acc += a.x * c.x + a.y * c.y + a.z * c.z + a.w * c.w;
    }
#pragma unroll
    for (int off = 16; off; off >>= 1) acc += __shfl_xor_sync(0xffffffffu, acc, off);
    if (lane == 0) g_ada[o] = acc + bias;
}

__global__ __launch_bounds__(256) void k_bh(const float* __restrict__ bias,
                                            const float* __restrict__ gam,
                                            const float* __restrict__ bet,
                                            const float* __restrict__ pw) {
    __shared__ float sw[H_DIM][P_DIM];
    __shared__ float sg[P_DIM], sb[P_DIM];
    for (int i = threadIdx.x; i < H_DIM * P_DIM; i += 256) sw[i >> 7][i & 127] = pw[i];
    if (threadIdx.x < P_DIM) { sg[threadIdx.x] = gam[threadIdx.x]; sb[threadIdx.x] = bet[threadIdx.x]; }
    __syncthreads();
    int warp = threadIdx.x >> 5, lane = threadIdx.x & 31;
    size_t idx = (size_t)blockIdx.x * 8 + warp;
    const float* src = bias + idx * P_DIM;
    float v[4];
#pragma unroll
    for (int i = 0; i < 4; i++) v[i] = src[lane + 32 * i];
    float s = v[0] + v[1] + v[2] + v[3];
#pragma unroll
    for (int o = 16; o; o >>= 1) s += __shfl_xor_sync(0xffffffffu, s, o);
    float mean = s * (1.0f / 128.0f);
    float q = 0.0f;
#pragma unroll
    for (int i = 0; i < 4; i++) { float d = v[i] - mean; q += d * d; }
#pragma unroll
    for (int o = 16; o; o >>= 1) q += __shfl_xor_sync(0xffffffffu, q, o);
    float rs = rsqrtf(q * (1.0f / 128.0f) + 1e-6f);
    float n[4];
#pragma unroll
    for (int i = 0; i < 4; i++) {
        int p = lane + 32 * i;
        n[i] = (v[i] - mean) * rs * sg[p] + sb[p];
    }
#pragma unroll
    for (int h = 0; h < H_DIM; h++) {
        float a = n[0] * sw[h][lane] + n[1] * sw[h][lane + 32] +
                  n[2] * sw[h][lane + 64] + n[3] * sw[h][lane + 96];
#pragma unroll
        for (int o = 16; o; o >>= 1) a += __shfl_xor_sync(0xffffffffu, a, o);
        if (lane == 0) g_bh[(size_t)h * L_DIM * L_DIM + idx] = a;
    }
}

// LN(x) modulated -> g_h2 (fp16 hi,lo pairs)
__global__ __launch_bounds__(256) void k_lnmod(const float* __restrict__ x, int ada_off) {
    int l = blockIdx.x;
    int t = threadIdx.x;
    const float* row = x + (size_t)l * E_DIM;
    float v0 = row[t], v1 = row[t + 256], v2 = row[t + 512];
    __shared__ float red[8];
    __shared__ float smean, srs;
    int lane = t & 31, warp = t >> 5;
    float s = v0 + v1 + v2;
#pragma unroll
    for (int o = 16; o; o >>= 1) s += __shfl_xor_sync(0xffffffffu, s, o);
    if (lane == 0) red[warp] = s;
    __syncthreads();
    if (t == 0) {
        float tot = 0;
        for (int i = 0; i < 8; i++) tot += red[i];
        smean = tot * (1.0f / 768.0f);
    }
    __syncthreads();
    float mean = smean;
    float d0 = v0 - mean, d1 = v1 - mean, d2 = v2 - mean;
    float q = d0 * d0 + d1 * d1 + d2 * d2;
#pragma unroll
    for (int o = 16; o; o >>= 1) q += __shfl_xor_sync(0xffffffffu, q, o);
    __syncthreads();
    if (lane == 0) red[warp] = q;
    __syncthreads();
    if (t == 0) {
        float tot = 0;
        for (int i = 0; i < 8; i++) tot += red[i];
        srs = rsqrtf(tot * (1.0f / 768.0f) + 1e-6f);
    }
    __syncthreads();
    float rs = srs;
    const float* sh = g_ada + ada_off;
    const float* sc = g_ada + ada_off + E_DIM;
    uint32_t* out2 = (uint32_t*)(g_h2 + (size_t)l * (2 * E_DIM));
#pragma unroll
    for (int i = 0; i < 3; i++) {
        int p = t + 256 * i;
        float d = (i == 0) ? d0 : (i == 1) ? d1 : d2;
        float v = d * rs * (1.0f + sc[p]) + sh[p];
        unsigned short hi, lo;
        f16split(v, hi, lo);
        out2[p] = pk2(hi, lo);
    }
}

__global__ __launch_bounds__(256) void k_softmax() {
    float* row = g_S + (size_t)blockIdx.x * L_DIM;
    int t = threadIdx.x;
    int lane = t & 31, warp = t >> 5;
    __shared__ float red[8];
    __shared__ float bval;
    float v[4];
#pragma unroll
    for (int i = 0; i < 4; i++) v[i] = row[t + 256 * i];
    float m = fmaxf(fmaxf(v[0], v[1]), fmaxf(v[2], v[3]));
#pragma unroll
    for (int o = 16; o; o >>= 1) m = fmaxf(m, __shfl_xor_sync(0xffffffffu, m, o));
    if (lane == 0) red[warp] = m;
    __syncthreads();
    if (t == 0) {
        float mm = red[0];
        for (int i = 1; i < 8; i++) mm = fmaxf(mm, red[i]);
        bval = mm;
    }
    __syncthreads();
    float mx = bval;
    float sum = 0;
#pragma unroll
    for (int i = 0; i < 4; i++) { v[i] = expf(v[i] - mx); sum += v[i]; }
#pragma unroll
    for (int o = 16; o; o >>= 1) sum += __shfl_xor_sync(0xffffffffu, sum, o);
    __syncthreads();
    if (lane == 0) red[warp] = sum;
    __syncthreads();
    if (t == 0) {
        float tot = 0;
        for (int i = 0; i < 8; i++) tot += red[i];
        bval = 1.0f / tot;
    }
    __syncthreads();
    float inv = bval;
#pragma unroll
    for (int i = 0; i < 4; i++) row[t + 256 * i] = v[i] * inv;
}

// ---------------- driver ------------------------------------------------------
extern "C" void kernel_launch(void* const* d_in, const int* in_sizes, int n_in,
                              void* d_out, int out_size) {
    const float* z      = (const float*)d_in[0];
    const float* t      = (const float*)d_in[1];
    const float* bias   = (const float*)d_in[2];
    const float* p2s_g  = (const float*)d_in[3];
    const float* p2s_b  = (const float*)d_in[4];
    const float* p2s_w  = (const float*)d_in[5];
    const float* t0_w   = (const float*)d_in[6];
    const float* t0_b   = (const float*)d_in[7];
    const float* t2_w   = (const float*)d_in[8];
    const float* t2_b   = (const float*)d_in[9];
    const float* proj_w = (const float*)d_in[10];
    const float* o_w    = (const float*)d_in[11];
    const float* o_b    = (const float*)d_in[12];
    const float* ada_w  = (const float*)d_in[13];
    const float* ada_b  = (const float*)d_in[14];
    const float* fc1_w  = (const float*)d_in[15];
    const float* fc1_b  = (const float*)d_in[16];
    const float* fc2_w  = (const float*)d_in[17];
    const float* fc2_b  = (const float*)d_in[18];
    const float* fin_aw = (const float*)d_in[19];
    const float* fin_ab = (const float*)d_in[20];
    const float* fin_w  = (const float*)d_in[21];
    const float* fin_b  = (const float*)d_in[22];
    float* out = (float*)d_out;

    float *px, *pqkv, *pada;
    __half *ph2, *py2, *pt12, *pw2;
    cudaGetSymbolAddress((void**)&px, g_x);
    cudaGetSymbolAddress((void**)&pqkv, g_qkv);
    cudaGetSymbolAddress((void**)&pada, g_ada);
    cudaGetSymbolAddress((void**)&ph2, g_h2);
    cudaGetSymbolAddress((void**)&py2, g_y2);
    cudaGetSymbolAddress((void**)&pt12, g_t12);
    cudaGetSymbolAddress((void**)&pw2, g_w2);

    const int SM128 = 3 * (10240 + 10240);
    const int SM64  = 3 * (10240 + 5120);
    cudaFuncSetAttribute(gemm_fp16<128, 0, 0, 0>, cudaFuncAttributeMaxDynamicSharedMemorySize, SM128);
    cudaFuncSetAttribute(gemm_fp16<64, 0, 1, 0>, cudaFuncAttributeMaxDynamicSharedMemorySize, SM64);
    cudaFuncSetAttribute(gemm_fp16<128, 1, 0, 1>, cudaFuncAttributeMaxDynamicSharedMemorySize, SM128);
    cudaFuncSetAttribute(gemm_fp16<64, 0, 0, 0>, cudaFuncAttributeMaxDynamicSharedMemorySize, SM64);
    cudaFuncSetAttribute(attn_scores_tc, cudaFuncAttributeMaxDynamicSharedMemorySize, SCR_SMEM);
    cudaFuncSetAttribute(attn_av_tc, cudaFuncAttributeMaxDynamicSharedMemorySize, AV_SMEM);

    // ---- weight conversion (hi,hi pairs) ----
    {
        int n;
        n = 8 * 3 * E_DIM * E_DIM / 8;
        k_cvt2<<<(n + 255) / 256, 256>>>(proj_w, pw2 + OFF_PROJ, n);
        n = 8 * E_DIM * E_DIM / 8;
        k_cvt2<<<(n + 255) / 256, 256>>>(o_w, pw2 + OFF_O, n);
        n = 8 * MLP_DIM * E_DIM / 8;
        k_cvt2<<<(n + 255) / 256, 256>>>(fc1_w, pw2 + OFF_FC1, n);
        n = 8 * E_DIM * MLP_DIM / 8;
        k_cvt2<<<(n + 255) / 256, 256>>>(fc2_w, pw2 + OFF_FC2, n);
        n = E_DIM * E_DIM / 8;
        k_cvt2<<<(n + 255) / 256, 256>>>(fin_w, pw2 + OFF_FIN, n);
    }

    k_copy<<<(L_DIM * E_DIM + 255) / 256, 256>>>(z, px, L_DIM * E_DIM);
    k_time1<<<3, 256>>>(t, t0_w, t0_b);
    k_time2<<<3, 256>>>(t2_w, t2_b);
    k_ada<<<(DEPTH * 6 * E_DIM + 2 * E_DIM) / 8, 256>>>(ada_w, ada_b, fin_aw, fin_ab);
    k_bh<<<L_DIM * L_DIM / 8, 256>>>(bias, p2s_g, p2s_b, p2s_w);

    const int K2E = 2 * E_DIM;     // 1536
    const int K2M = 2 * MLP_DIM;   // 6144

    for (int d = 0; d < DEPTH; d++) {
        int ao = d * 6 * E_DIM;
        k_lnmod<<<L_DIM, 256>>>(px, ao);
        // qkv = h @ pw^T
        gemm_fp16<128, 0, 0, 0><<<dim3(18, 8), 256, SM128>>>(
            ph2, pw2 + OFF_PROJ + (size_t)d * 3 * E_DIM * K2E, nullptr, nullptr, nullptr,
            pqkv, nullptr, 3 * E_DIM, K2E);
        attn_scores_tc<<<dim3(8, 8, 16), 256, SCR_SMEM>>>();
        k_softmax<<<H_DIM * L_DIM, 256>>>();
        attn_av_tc<<<dim3(8, 16), 128, AV_SMEM>>>();
        // x += g1 * (y @ ow^T + ob)
        gemm_fp16<64, 0, 1, 0><<<dim3(12, 8), 256, SM64>>>(
            py2, pw2 + OFF_O + (size_t)d * E_DIM * K2E, o_b + d * E_DIM,
            px, pada + ao + 2 * E_DIM, px, nullptr, E_DIM, K2E);
        k_lnmod<<<L_DIM, 256>>>(px, ao + 3 * E_DIM);
        // t12 = split(gelu(h2 @ f1w^T + f1b))
        gemm_fp16<128, 1, 0, 1><<<dim3(24, 8), 256, SM128>>>(
            ph2, pw2 + OFF_FC1 + (size_t)d * MLP_DIM * K2E, fc1_b + d * MLP_DIM,
            nullptr, nullptr, nullptr, pt12, MLP_DIM, K2E);
        // x += g2 * (t1 @ f2w^T + f2b)
        gemm_fp16<64, 0, 1, 0><<<dim3(12, 8), 256, SM64>>>(
            pt12, pw2 + OFF_FC2 + (size_t)d * E_DIM * K2M, fc2_b + d * E_DIM,
            px, pada + ao + 5 * E_DIM, px, nullptr, E_DIM, K2M);
    }
    k_lnmod<<<L_DIM, 256>>>(px, DEPTH * 6 * E_DIM);
    gemm_fp16<64, 0, 0, 0><<<dim3(12, 8), 256, SM64>>>(
        ph2, pw2 + OFF_FIN, fin_b, nullptr, nullptr, out, nullptr, E_DIM, K2E);
    (void)in_sizes; (void)n_in; (void)out_size;
}

// round 14
// speedup vs baseline: 2.6125x; 1.6821x over previous
#include <cuda_runtime.h>
#include <cuda_fp16.h>
#include <cstdint>
#include <math.h>

#define L_DIM 1024
#define E_DIM 768
#define P_DIM 128
#define H_DIM 16
#define HD_DIM 48
#define DEPTH 8
#define MLP_DIM 3072

// ---------------- scratch (device globals) ---------------------------------
__device__ float g_x[L_DIM * E_DIM];
__device__ float g_qkv[L_DIM * 3 * E_DIM];
__device__ float g_bh[(size_t)H_DIM * L_DIM * L_DIM];
__device__ float g_hidden[E_DIM];
__device__ float g_cs[E_DIM];
__device__ float g_ada[DEPTH * 6 * E_DIM + 2 * E_DIM];

// fp16 buffers
__device__ __align__(16) __half g_h2[L_DIM * 2 * E_DIM];          // (hi,lo) pairs
__device__ __align__(16) __half g_h1[L_DIM * E_DIM];              // hi only
__device__ __align__(16) __half g_y2[L_DIM * 2 * E_DIM];          // (hi,lo) pairs
__device__ __align__(16) __half g_t11[(size_t)L_DIM * MLP_DIM];   // hi only
// attention-prepped operands
__device__ __align__(16) __half g_q3[(size_t)H_DIM * L_DIM * 144];  // (hi,lo,hi), pre-scaled
__device__ __align__(16) __half g_k3[(size_t)H_DIM * L_DIM * 144];  // (hi,hi,lo)
__device__ __align__(16) __half g_vt[(size_t)H_DIM * HD_DIM * L_DIM]; // hi, transposed
// weights (pairs): proj | o | fin
#define OFF_PROJ 0ULL
#define OFF_O    28311552ULL
#define OFF_FIN  37748736ULL
#define W2_TOTAL 38928384ULL
__device__ __align__(16) __half g_w2[W2_TOTAL];
// weights (single): fc1 | fc2
#define OFF_FC1  0ULL
#define OFF_FC2  18874368ULL
#define W1_TOTAL 37748736ULL
__device__ __align__(16) __half g_w1[W1_TOTAL];

// ---------------- helpers ----------------------------------------------------
__device__ __forceinline__ uint32_t smem_u32(const void* p) {
    uint32_t a;
    asm("{ .reg .u64 t; cvta.to.shared.u64 t, %1; cvt.u32.u64 %0, t; }" : "=r"(a) : "l"(p));
    return a;
}
__device__ __forceinline__ uint32_t lds32(uint32_t a) {
    uint32_t v;
    asm volatile("ld.shared.b32 %0, [%1];" : "=r"(v) : "r"(a));
    return v;
}
__device__ __forceinline__ void mma16816(float* c, const uint32_t* a, uint32_t b0, uint32_t b1) {
    asm volatile(
        "mma.sync.aligned.m16n8k16.row.col.f32.f16.f16.f32 "
        "{%0,%1,%2,%3}, {%4,%5,%6,%7}, {%8,%9}, {%0,%1,%2,%3};"
        : "+f"(c[0]), "+f"(c[1]), "+f"(c[2]), "+f"(c[3])
        : "r"(a[0]), "r"(a[1]), "r"(a[2]), "r"(a[3]), "r"(b0), "r"(b1));
}
__device__ __forceinline__ void cpasync16(uint32_t dst, const void* src) {
    asm volatile("cp.async.cg.shared.global [%0], [%1], 16;" :: "r"(dst), "l"(src));
}
__device__ __forceinline__ void f16split(float v, unsigned short& hi, unsigned short& lo) {
    __half h = __float2half_rn(v);
    __half l = __float2half_rn(v - __half2float(h));
    hi = __half_as_ushort(h);
    lo = __half_as_ushort(l);
}
__device__ __forceinline__ unsigned short f16hi(float v) {
    return __half_as_ushort(__float2half_rn(v));
}
__device__ __forceinline__ uint32_t pk2(unsigned short a, unsigned short b) {
    return (uint32_t)a | ((uint32_t)b << 16);
}
__device__ __forceinline__ float gelu_f(float v) {
    float c = v + 0.044715f * v * v * v;
    return 0.5f * v * (1.0f + tanhf(0.7978845608028654f * c));
}
__device__ __forceinline__ float silu_f(float x) { return x / (1.0f + expf(-x)); }

// ---------------- weight conversions -----------------------------------------
__global__ void k_cvt2(const float* __restrict__ src, __half* __restrict__ dst, int n8) {
    int t = blockIdx.x * blockDim.x + threadIdx.x;
    if (t >= n8) return;
    const float4* s4 = (const float4*)src + (size_t)t * 2;
    float4 p = s4[0], q = s4[1];
    float v[8] = {p.x, p.y, p.z, p.w, q.x, q.y, q.z, q.w};
    uint32_t o[8];
#pragma unroll
    for (int e = 0; e < 8; e++) {
        unsigned short hi = f16hi(v[e]);
        o[e] = pk2(hi, hi);
    }
    uint4* d = (uint4*)((char*)dst + (size_t)t * 32);
    d[0] = make_uint4(o[0], o[1], o[2], o[3]);
    d[1] = make_uint4(o[4], o[5], o[6], o[7]);
}
__global__ void k_cvt1(const float* __restrict__ src, __half* __restrict__ dst, int n8) {
    int t = blockIdx.x * blockDim.x + threadIdx.x;
    if (t >= n8) return;
    const float4* s4 = (const float4*)src + (size_t)t * 2;
    float4 p = s4[0], q = s4[1];
    uint4 w;
    w.x = pk2(f16hi(p.x), f16hi(p.y));
    w.y = pk2(f16hi(p.z), f16hi(p.w));
    w.z = pk2(f16hi(q.x), f16hi(q.y));
    w.w = pk2(f16hi(q.z), f16hi(q.w));
    *(uint4*)((char*)dst + (size_t)t * 16) = w;
}

// ---------------- tensor-core GEMM -------------------------------------------
// C[M=1024, Ntot] = A[M,K2] @ W[Ntot,K2]^T
// OMODE: 0 none, 1 write fp16 (hi,lo) pairs, 2 write fp16 hi only
template <int NT, int ACT, int RES, int OMODE>
__global__ void __launch_bounds__(256) gemm_fp16(
    const __half* __restrict__ A2, const __half* __restrict__ W2,
    const float* __restrict__ bias, const float* __restrict__ res,
    const float* __restrict__ gate, float* __restrict__ Cf,
    __half* __restrict__ Ch, int Ntot, int K2) {
    constexpr int SA_B = 80;
    constexpr int A_BYTES = 128 * SA_B;
    constexpr int W_BYTES = NT * SA_B;
    constexpr int STAGE = A_BYTES + W_BYTES;
    constexpr int PIPE = 3;
    extern __shared__ char smem[];
    uint32_t sbase = smem_u32(smem);

    const int tid = threadIdx.x;
    const int wid = tid >> 5, lane = tid & 31;
    const int g = lane >> 2, tig = lane & 3;
    const int bm = blockIdx.y * 128, bn = blockIdx.x * NT;

    constexpr int WN_WARPS = (NT == 128) ? 4 : 2;
    constexpr int WM = (NT == 128) ? 64 : 32;
    constexpr int WN = 32;
    constexpr int MA = WM / 16;
    constexpr int NA = WN / 8;
    const int wm0 = (wid / WN_WARPS) * WM;
    const int wn0 = (wid % WN_WARPS) * WN;

    float acc[MA][NA][4] = {};
    const int S = K2 >> 5;

    auto issue_stage = [&](int s) {
        if (s < S) {
            int buf = s % PIPE;
            uint32_t sA = sbase + buf * STAGE;
            uint32_t sW = sA + A_BYTES;
            int k0 = s << 5;
#pragma unroll
            for (int t2 = 0; t2 < 2; t2++) {
                int chunk = tid + t2 * 256;
                int row = chunk >> 2, c4 = chunk & 3;
                cpasync16(sA + row * SA_B + c4 * 16, A2 + (size_t)(bm + row) * K2 + k0 + c4 * 8);
            }
#pragma unroll
            for (int t2 = 0; t2 < NT / 64; t2++) {
                int chunk = tid + t2 * 256;
                int row = chunk >> 2, c4 = chunk & 3;
                cpasync16(sW + row * SA_B + c4 * 16, W2 + (size_t)(bn + row) * K2 + k0 + c4 * 8);
            }
        }
        asm volatile("cp.async.commit_group;" ::: "memory");
    };

    issue_stage(0);
    issue_stage(1);

    for (int s = 0; s < S; s++) {
        asm volatile("cp.async.wait_group %0;" ::"n"(PIPE - 2) : "memory");
        __syncthreads();
        int buf = s % PIPE;
        uint32_t sA = sbase + buf * STAGE + wm0 * SA_B;
        uint32_t sW = sbase + buf * STAGE + A_BYTES + wn0 * SA_B;
#pragma unroll
        for (int kk = 0; kk < 2; kk++) {
            int kb = (kk * 16 + 2 * tig) * 2;
            uint32_t a[MA][4];
#pragma unroll
            for (int im = 0; im < MA; im++) {
                uint32_t r = sA + (im * 16 + g) * SA_B + kb;
                a[im][0] = lds32(r);
                a[im][1] = lds32(r + 8 * SA_B);
                a[im][2] = lds32(r + 16);
                a[im][3] = lds32(r + 8 * SA_B + 16);
            }
#pragma unroll
            for (int in2 = 0; in2 < NA; in2++) {
                uint32_t rb = sW + (in2 * 8 + g) * SA_B + kb;
                uint32_t b0 = lds32(rb), b1 = lds32(rb + 16);
#pragma unroll
                for (int im = 0; im < MA; im++) mma16816(acc[im][in2], a[im], b0, b1);
            }
        }
        issue_stage(s + PIPE - 1);
    }

#pragma unroll
    for (int im = 0; im < MA; im++) {
#pragma unroll
        for (int in2 = 0; in2 < NA; in2++) {
            int r0 = bm + wm0 + im * 16 + g;
            int c0 = bn + wn0 + in2 * 8 + 2 * tig;
            float bv0 = bias ? bias[c0] : 0.0f;
            float bv1 = bias ? bias[c0 + 1] : 0.0f;
            float gv0 = 0.0f, gv1 = 0.0f;
            if (RES) { gv0 = gate[c0]; gv1 = gate[c0 + 1]; }
#pragma unroll
            for (int rh = 0; rh < 2; rh++) {
                int r = r0 + rh * 8;
                float v0 = acc[im][in2][rh * 2 + 0] + bv0;
                float v1 = acc[im][in2][rh * 2 + 1] + bv1;
                if (ACT) { v0 = gelu_f(v0); v1 = gelu_f(v1); }
                if (RES) {
                    v0 = res[(size_t)r * Ntot + c0] + gv0 * v0;
                    v1 = res[(size_t)r * Ntot + c0 + 1] + gv1 * v1;
                }
                if (Cf) {
                    Cf[(size_t)r * Ntot + c0] = v0;
                    Cf[(size_t)r * Ntot + c0 + 1] = v1;
                }
                if (OMODE == 1) {
                    unsigned short h0, l0, h1, l1;
                    f16split(v0, h0, l0);
                    f16split(v1, h1, l1);
                    uint32_t* dp = (uint32_t*)(Ch + (size_t)r * 2 * Ntot);
                    dp[c0] = pk2(h0, l0);
                    dp[c0 + 1] = pk2(h1, l1);
                } else if (OMODE == 2) {
                    uint32_t* dp = (uint32_t*)(Ch + (size_t)r * Ntot);
                    dp[c0 >> 1] = pk2(f16hi(v0), f16hi(v1));
                }
            }
        }
    }
}

// ---------------- attention prep: qkv f32 -> split fp16 operands ------------
__global__ void __launch_bounds__(256) k_prep() {
    const float scale = 0.14433756729740643f;
    int idx = blockIdx.x * 256 + threadIdx.x;   // over H*L*48
    int c = idx % 48;
    int l = (idx / 48) & 1023;
    int h = idx / (48 * 1024);
    // q (scaled, hi/lo/hi) and k (hi/hi/lo)
    float q = g_qkv[(size_t)l * 2304 + h * 144 + c] * scale;
    unsigned short hi, lo;
    f16split(q, hi, lo);
    __half* qp = g_q3 + ((size_t)(h << 10) + l) * 144 + 3 * c;
    qp[0] = __ushort_as_half(hi);
    qp[1] = __ushort_as_half(lo);
    qp[2] = __ushort_as_half(hi);
    float k = g_qkv[(size_t)l * 2304 + h * 144 + 48 + c];
    f16split(k, hi, lo);
    __half* kp = g_k3 + ((size_t)(h << 10) + l) * 144 + 3 * c;
    kp[0] = __ushort_as_half(hi);
    kp[1] = __ushort_as_half(hi);
    kp[2] = __ushort_as_half(lo);
    // v transposed, coalesced write mapping: (h, c, m) with m fastest
    int m = idx & 1023;
    int c2 = (idx >> 10) % 48;
    int h2 = idx / (48 * 1024);
    float v = g_qkv[(size_t)m * 2304 + h2 * 144 + 96 + c2];
    g_vt[((size_t)h2 * 48 + c2) * 1024 + m] = __float2half_rn(v);
}

// ---------------- fused flash attention --------------------------------------
// grid (8, 16): 128 l-rows x head. 8 warps x 16 rows. m chunks of 128.
#define FQ_STRIDE 304
#define FV_STRIDE 272
#define FK_OFF (128 * FQ_STRIDE)          // 38912
#define FSTAGE (128 * FQ_STRIDE + 48 * FV_STRIDE)  // 51968
#define FLASH_SMEM (FK_OFF + 2 * FSTAGE)  // 142848
__global__ void __launch_bounds__(256) flash_attn() {
    int h = blockIdx.y, lb = blockIdx.x * 128;
    extern __shared__ char smem[];
    uint32_t sQ = smem_u32(smem);
    int tid = threadIdx.x;
    int wid = tid >> 5, lane = tid & 31;
    int g = lane >> 2, tig = lane & 3;

    const __half* q3 = g_q3 + ((size_t)(h << 10) + lb) * 144;
    const __half* k3 = g_k3 + (size_t)(h << 10) * 144;
    const __half* vt = g_vt + (size_t)h * 48 * 1024;

    // Q tile (group 0)
    for (int i = tid; i < 128 * 18; i += 256) {
        int r = i / 18, c16 = i % 18;
        cpasync16(sQ + r * FQ_STRIDE + c16 * 16, q3 + (size_t)r * 144 + c16 * 8);
    }
    asm volatile("cp.async.commit_group;" ::: "memory");

    auto issueKV = [&](int mc) {
        uint32_t sS = sQ + FK_OFF + (mc & 1) * FSTAGE;
        for (int i = tid; i < 128 * 18; i += 256) {
            int r = i / 18, c16 = i % 18;
            cpasync16(sS + r * FQ_STRIDE + c16 * 16, k3 + (size_t)(mc * 128 + r) * 144 + c16 * 8);
        }
        uint32_t sV = sS + FK_OFF;
        for (int i = tid; i < 48 * 16; i += 256) {
            int r = i / 16, c16 = i % 16;
            cpasync16(sV + r * FV_STRIDE + c16 * 16, vt + (size_t)r * 1024 + mc * 128 + c16 * 8);
        }
        asm volatile("cp.async.commit_group;" ::: "memory");
    };
    issueKV(0);

    float m0 = -1e30f, m1 = -1e30f, ls0 = 0.0f, ls1 = 0.0f;
    float oacc[6][4] = {};
    const float* bhrow0 = g_bh + (size_t)h * L_DIM * L_DIM + (size_t)(lb + wid * 16 + g) * L_DIM;
    const float* bhrow1 = bhrow0 + 8 * L_DIM;
    uint32_t sQw = sQ + (wid * 16 + g) * FQ_STRIDE;

    for (int mc = 0; mc < 8; mc++) {
        if (mc < 7) issueKV(mc + 1);
        if (mc < 7) { asm volatile("cp.async.wait_group 1;" ::: "memory"); }
        else        { asm volatile("cp.async.wait_group 0;" ::: "memory"); }
        __syncthreads();
        uint32_t sK = sQ + FK_OFF + (mc & 1) * FSTAGE;
        uint32_t sV = sK + FK_OFF;

        float sacc[16][4] = {};
#pragma unroll
        for (int ks = 0; ks < 9; ks++) {
            int kb = ks * 32 + tig * 4;
            uint32_t a[4];
            a[0] = lds32(sQw + kb);
            a[1] = lds32(sQw + 8 * FQ_STRIDE + kb);
            a[2] = lds32(sQw + kb + 16);
            a[3] = lds32(sQw + 8 * FQ_STRIDE + kb + 16);
#pragma unroll
            for (int j = 0; j < 16; j++) {
                uint32_t rb = sK + (j * 8 + g) * FQ_STRIDE + kb;
                uint32_t b0 = lds32(rb), b1 = lds32(rb + 16);
                mma16816(sacc[j], a, b0, b1);
            }
        }
        // add bias, row stats
        float r0max = -1e30f, r1max = -1e30f;
#pragma unroll
        for (int j = 0; j < 16; j++) {
            int col = mc * 128 + j * 8 + 2 * tig;
            float2 b0 = *(const float2*)&bhrow0[col];
            float2 b1 = *(const float2*)&bhrow1[col];
            sacc[j][0] += b0.x; sacc[j][1] += b0.y;
            sacc[j][2] += b1.x; sacc[j][3] += b1.y;
            r0max = fmaxf(r0max, fmaxf(sacc[j][0], sacc[j][1]));
            r1max = fmaxf(r1max, fmaxf(sacc[j][2], sacc[j][3]));
        }
        r0max = fmaxf(r0max, __shfl_xor_sync(0xffffffffu, r0max, 1));
        r0max = fmaxf(r0max, __shfl_xor_sync(0xffffffffu, r0max, 2));
        r1max = fmaxf(r1max, __shfl_xor_sync(0xffffffffu, r1max, 1));
        r1max = fmaxf(r1max, __shfl_xor_sync(0xffffffffu, r1max, 2));
        float mn0 = fmaxf(m0, r0max), mn1 = fmaxf(m1, r1max);
        float al0 = __expf(m0 - mn0), al1 = __expf(m1 - mn1);
        float ps0 = 0.0f, ps1 = 0.0f;
#pragma unroll
        for (int j = 0; j < 16; j++) {
            sacc[j][0] = __expf(sacc[j][0] - mn0);
            sacc[j][1] = __expf(sacc[j][1] - mn0);
            sacc[j][2] = __expf(sacc[j][2] - mn1);
            sacc[j][3] = __expf(sacc[j][3] - mn1);
            ps0 += sacc[j][0] + sacc[j][1];
            ps1 += sacc[j][2] + sacc[j][3];
        }
        ps0 += __shfl_xor_sync(0xffffffffu, ps0, 1);
        ps0 += __shfl_xor_sync(0xffffffffu, ps0, 2);
        ps1 += __shfl_xor_sync(0xffffffffu, ps1, 1);
        ps1 += __shfl_xor_sync(0xffffffffu, ps1, 2);
        ls0 = ls0 * al0 + ps0;
        ls1 = ls1 * al1 + ps1;
        m0 = mn0; m1 = mn1;
#pragma unroll
        for (int jo = 0; jo < 6; jo++) {
            oacc[jo][0] *= al0; oacc[jo][1] *= al0;
            oacc[jo][2] *= al1; oacc[jo][3] *= al1;
        }
        // AV: P from registers (C-frag == A-frag), V from smem
#pragma unroll
        for (int kc = 0; kc < 8; kc++) {
            uint32_t a[4];
            a[0] = pk2(f16hi(sacc[2 * kc][0]), f16hi(sacc[2 * kc][1]));
            a[1] = pk2(f16hi(sacc[2 * kc][2]), f16hi(sacc[2 * kc][3]));
            a[2] = pk2(f16hi(sacc[2 * kc + 1][0]), f16hi(sacc[2 * kc + 1][1]));
            a[3] = pk2(f16hi(sacc[2 * kc + 1][2]), f16hi(sacc[2 * kc + 1][3]));
            int kb = kc * 32 + tig * 4;
#pragma unroll
            for (int jo = 0; jo < 6; jo++) {
                uint32_t rb = sV + (jo * 8 + g) * FV_STRIDE + kb;
                uint32_t b0 = lds32(rb), b1 = lds32(rb + 16);
                mma16816(oacc[jo], a, b0, b1);
            }
        }
        __syncthreads();
    }
    // epilogue -> g_y2 (hi,lo) pairs
    float inv0 = 1.0f / ls0, inv1 = 1.0f / ls1;
    int r0 = lb + wid * 16 + g;
#pragma unroll
    for (int jo = 0; jo < 6; jo++) {
        int c0 = h * 48 + jo * 8 + 2 * tig;
        unsigned short hh, ll;
        uint32_t* dp0 = (uint32_t*)(g_y2 + (size_t)r0 * 2 * E_DIM);
        uint32_t* dp1 = (uint32_t*)(g_y2 + (size_t)(r0 + 8) * 2 * E_DIM);
        float v;
        v = oacc[jo][0] * inv0; f16split(v, hh, ll); dp0[c0] = pk2(hh, ll);
        v = oacc[jo][1] * inv0; f16split(v, hh, ll); dp0[c0 + 1] = pk2(hh, ll);
        v = oacc[jo][2] * inv1; f16split(v, hh, ll); dp1[c0] = pk2(hh, ll);
        v = oacc[jo][3] * inv1; f16split(v, hh, ll); dp1[c0 + 1] = pk2(hh, ll);
    }
}

// ---------------- small kernels ---------------------------------------------
__global__ void k_copy(const float* __restrict__ src, float* __restrict__ dst, int n) {
    int i = blockIdx.x * blockDim.x + threadIdx.x;
    if (i < n) dst[i] = src[i];
}

__global__ void k_time1(const float* __restrict__ t, const float* __restrict__ w,
                        const float* __restrict__ b) {
    int i = blockIdx.x * blockDim.x + threadIdx.x;
    if (i >= E_DIM) return;
    float tv = t[0];
    float acc = 0.0f;
    const float kfac = -9.210340371976184f / 128.0f;
    for (int j = 0; j < 128; j++) {
        float f = expf(kfac * (float)j);
        float a = tv * f;
        acc += cosf(a) * w[i * 256 + j] + sinf(a) * w[i * 256 + 128 + j];
    }
    g_hidden[i] = silu_f(acc + b[i]);
}

__global__ void k_time2(const float* __restrict__ w, const float* __restrict__ b) {
    int i = blockIdx.x * blockDim.x + threadIdx.x;
    if (i >= E_DIM) return;
    float acc = 0.0f;
    for (int j = 0; j < E_DIM; j++) acc += g_hidden[j] * w[i * E_DIM + j];
    g_cs[i] = silu_f(acc + b[i]);
}

__global__ __launch_bounds__(256) void k_ada(const float* __restrict__ aw,
                                             const float* __restrict__ ab,
                                             const float* __restrict__ fw,
                                             const float* __restrict__ fb) {
    __shared__ float4 scs[192];
    for (int i = threadIdx.x; i < 192; i += 256) scs[i] = ((const float4*)g_cs)[i];
    __syncthreads();
    int wid = threadIdx.x >> 5, lane = threadIdx.x & 31;
    int o = blockIdx.x * 8 + wid;
    const int NB = DEPTH * 6 * E_DIM;
    if (o >= NB + 2 * E_DIM) return;
    const float* w;
    float bias;
    if (o < NB) { w = aw + (size_t)o * E_DIM; bias = ab[o]; }
    else        { w = fw + (size_t)(o - NB) * E_DIM; bias = fb[o - NB]; }
    const float4* w4 = (const float4*)w;
    float acc = 0.0f;
    for (int j = lane; j < 192; j += 32) {
        float4 a = w4[j];
        float4 c = scs[j];
        acc += a.x * c.x + a.y * c.y + a.z * c.z + a.w * c.w;
    }
#pragma unroll
    for (int off = 16; off; off >>= 1) acc += __shfl_xor_sync(0xffffffffu, acc, off);
    if (lane == 0) g_ada[o] = acc + bias;
}

__global__ __launch_bounds__(256) void k_bh(const float* __restrict__ bias,
                                            const float* __restrict__ gam,
                                            const float* __restrict__ bet,
                                            const float* __restrict__ pw) {
    __shared__ float sw[H_DIM][P_DIM];
    __shared__ float sg[P_DIM], sb[P_DIM];
    for (int i = threadIdx.x; i < H_DIM * P_DIM; i += 256) sw[i >> 7][i & 127] = pw[i];
    if (threadIdx.x < P_DIM) { sg[threadIdx.x] = gam[threadIdx.x]; sb[threadIdx.x] = bet[threadIdx.x]; }
    __syncthreads();
    int warp = threadIdx.x >> 5, lane = threadIdx.x & 31;
    size_t idx = (size_t)blockIdx.x * 8 + warp;
    const float* src = bias + idx * P_DIM;
    float v[4];
#pragma unroll
    for (int i = 0; i < 4; i++) v[i] = src[lane + 32 * i];
    float s = v[0] + v[1] + v[2] + v[3];
#pragma unroll
    for (int o = 16; o; o >>= 1) s += __shfl_xor_sync(0xffffffffu, s, o);
    float mean = s * (1.0f / 128.0f);
    float q = 0.0f;
#pragma unroll
    for (int i = 0; i < 4; i++) { float d = v[i] - mean; q += d * d; }
#pragma unroll
    for (int o = 16; o; o >>= 1) q += __shfl_xor_sync(0xffffffffu, q, o);
    float rs = rsqrtf(q * (1.0f / 128.0f) + 1e-6f);
    float n[4];
#pragma unroll
    for (int i = 0; i < 4; i++) {
        int p = lane + 32 * i;
        n[i] = (v[i] - mean) * rs * sg[p] + sb[p];
    }
#pragma unroll
    for (int h = 0; h < H_DIM; h++) {
        float a = n[0] * sw[h][lane] + n[1] * sw[h][lane + 32] +
                  n[2] * sw[h][lane + 64] + n[3] * sw[h][lane + 96];
#pragma unroll
        for (int o = 16; o; o >>= 1) a += __shfl_xor_sync(0xffffffffu, a, o);
        if (lane == 0) g_bh[(size_t)h * L_DIM * L_DIM + idx] = a;
    }
}

// LN(x) modulated -> PAT=2: g_h2 (hi,lo pairs); PAT=1: g_h1 (hi only)
template <int PAT>
__global__ __launch_bounds__(256) void k_lnmod(const float* __restrict__ x, int ada_off) {
    int l = blockIdx.x;
    int t = threadIdx.x;
    const float* row = x + (size_t)l * E_DIM;
    float v0 = row[t], v1 = row[t + 256], v2 = row[t + 512];
    __shared__ float red[8];
    __shared__ float smean, srs;
    int lane = t & 31, warp = t >> 5;
    float s = v0 + v1 + v2;
#pragma unroll
    for (int o = 16; o; o >>= 1) s += __shfl_xor_sync(0xffffffffu, s, o);
    if (lane == 0) red[warp] = s;
    __syncthreads();
    if (t == 0) {
        float tot = 0;
        for (int i = 0; i < 8; i++) tot += red[i];
        smean = tot * (1.0f / 768.0f);
    }
    __syncthreads();
    float mean = smean;
    float d0 = v0 - mean, d1 = v1 - mean, d2 = v2 - mean;
    float q = d0 * d0 + d1 * d1 + d2 * d2;
#pragma unroll
    for (int o = 16; o; o >>= 1) q += __shfl_xor_sync(0xffffffffu, q, o);
    __syncthreads();
    if (lane == 0) red[warp] = q;
    __syncthreads();
    if (t == 0) {
        float tot = 0;
        for (int i = 0; i < 8; i++) tot += red[i];
        srs = rsqrtf(tot * (1.0f / 768.0f) + 1e-6f);
    }
    __syncthreads();
    float rs = srs;
    const float* sh = g_ada + ada_off;
    const float* sc = g_ada + ada_off + E_DIM;
#pragma unroll
    for (int i = 0; i < 3; i++) {
        int p = t + 256 * i;
        float d = (i == 0) ? d0 : (i == 1) ? d1 : d2;
        float v = d * rs * (1.0f + sc[p]) + sh[p];
        if (PAT == 2) {
            unsigned short hi, lo;
            f16split(v, hi, lo);
            ((uint32_t*)(g_h2 + (size_t)l * (2 * E_DIM)))[p] = pk2(hi, lo);
        } else {
            g_h1[(size_t)l * E_DIM + p] = __float2half_rn(v);
        }
    }
}

// ---------------- driver ------------------------------------------------------
extern "C" void kernel_launch(void* const* d_in, const int* in_sizes, int n_in,
                              void* d_out, int out_size) {
    const float* z      = (const float*)d_in[0];
    const float* t      = (const float*)d_in[1];
    const float* bias   = (const float*)d_in[2];
    const float* p2s_g  = (const float*)d_in[3];
    const float* p2s_b  = (const float*)d_in[4];
    const float* p2s_w  = (const float*)d_in[5];
    const float* t0_w   = (const float*)d_in[6];
    const float* t0_b   = (const float*)d_in[7];
    const float* t2_w   = (const float*)d_in[8];
    const float* t2_b   = (const float*)d_in[9];
    const float* proj_w = (const float*)d_in[10];
    const float* o_w    = (const float*)d_in[11];
    const float* o_b    = (const float*)d_in[12];
    const float* ada_w  = (const float*)d_in[13];
    const float* ada_b  = (const float*)d_in[14];
    const float* fc1_w  = (const float*)d_in[15];
    const float* fc1_b  = (const float*)d_in[16];
    const float* fc2_w  = (const float*)d_in[17];
    const float* fc2_b  = (const float*)d_in[18];
    const float* fin_aw = (const float*)d_in[19];
    const float* fin_ab = (const float*)d_in[20];
    const float* fin_w  = (const float*)d_in[21];
    const float* fin_b  = (const float*)d_in[22];
    float* out = (float*)d_out;

    float *px, *pqkv, *pada;
    __half *ph2, *ph1, *py2, *pt11, *pw2, *pw1;
    cudaGetSymbolAddress((void**)&px, g_x);
    cudaGetSymbolAddress((void**)&pqkv, g_qkv);
    cudaGetSymbolAddress((void**)&pada, g_ada);
    cudaGetSymbolAddress((void**)&ph2, g_h2);
    cudaGetSymbolAddress((void**)&ph1, g_h1);
    cudaGetSymbolAddress((void**)&py2, g_y2);
    cudaGetSymbolAddress((void**)&pt11, g_t11);
    cudaGetSymbolAddress((void**)&pw2, g_w2);
    cudaGetSymbolAddress((void**)&pw1, g_w1);

    const int SM128 = 3 * (10240 + 10240);
    const int SM64  = 3 * (10240 + 5120);
    cudaFuncSetAttribute(gemm_fp16<128, 0, 0, 0>, cudaFuncAttributeMaxDynamicSharedMemorySize, SM128);
    cudaFuncSetAttribute(gemm_fp16<64, 0, 1, 0>, cudaFuncAttributeMaxDynamicSharedMemorySize, SM64);
    cudaFuncSetAttribute(gemm_fp16<128, 1, 0, 2>, cudaFuncAttributeMaxDynamicSharedMemorySize, SM128);
    cudaFuncSetAttribute(gemm_fp16<64, 0, 0, 0>, cudaFuncAttributeMaxDynamicSharedMemorySize, SM64);
    cudaFuncSetAttribute(flash_attn, cudaFuncAttributeMaxDynamicSharedMemorySize, FLASH_SMEM);

    // ---- weight conversion ----
    {
        int n;
        n = 8 * 3 * E_DIM * E_DIM / 8;
        k_cvt2<<<(n + 255) / 256, 256>>>(proj_w, pw2 + OFF_PROJ, n);
        n = 8 * E_DIM * E_DIM / 8;
        k_cvt2<<<(n + 255) / 256, 256>>>(o_w, pw2 + OFF_O, n);
        n = E_DIM * E_DIM / 8;
        k_cvt2<<<(n + 255) / 256, 256>>>(fin_w, pw2 + OFF_FIN, n);
        n = 8 * MLP_DIM * E_DIM / 8;
        k_cvt1<<<(n + 255) / 256, 256>>>(fc1_w, pw1 + OFF_FC1, n);
        k_cvt1<<<(n + 255) / 256, 256>>>(fc2_w, pw1 + OFF_FC2, n);
    }

    k_copy<<<(L_DIM * E_DIM + 255) / 256, 256>>>(z, px, L_DIM * E_DIM);
    k_time1<<<3, 256>>>(t, t0_w, t0_b);
    k_time2<<<3, 256>>>(t2_w, t2_b);
    k_ada<<<(DEPTH * 6 * E_DIM + 2 * E_DIM) / 8, 256>>>(ada_w, ada_b, fin_aw, fin_ab);
    k_bh<<<L_DIM * L_DIM / 8, 256>>>(bias, p2s_g, p2s_b, p2s_w);

    const int K2E = 2 * E_DIM;   // 1536

    for (int d = 0; d < DEPTH; d++) {
        int ao = d * 6 * E_DIM;
        k_lnmod<2><<<L_DIM, 256>>>(px, ao);
        // qkv = h @ pw^T (f32)
        gemm_fp16<128, 0, 0, 0><<<dim3(18, 8), 256, SM128>>>(
            ph2, pw2 + OFF_PROJ + (size_t)d * 3 * E_DIM * K2E, nullptr, nullptr, nullptr,
            pqkv, nullptr, 3 * E_DIM, K2E);
        // split q/k/v into mma operands, then fused attention
        k_prep<<<H_DIM * L_DIM * 48 / 256, 256>>>();
        flash_attn<<<dim3(8, H_DIM), 256, FLASH_SMEM>>>();
        // x += g1 * (y @ ow^T + ob)
        gemm_fp16<64, 0, 1, 0><<<dim3(12, 8), 256, SM64>>>(
            py2, pw2 + OFF_O + (size_t)d * E_DIM * K2E, o_b + d * E_DIM,
            px, pada + ao + 2 * E_DIM, px, nullptr, E_DIM, K2E);
        k_lnmod<1><<<L_DIM, 256>>>(px, ao + 3 * E_DIM);
        // t1 = gelu(h1 @ f1w^T + f1b), fp16 single K=768
        gemm_fp16<128, 1, 0, 2><<<dim3(24, 8), 256, SM128>>>(
            ph1, pw1 + OFF_FC1 + (size_t)d * MLP_DIM * E_DIM, fc1_b + d * MLP_DIM,
            nullptr, nullptr, nullptr, pt11, MLP_DIM, E_DIM);
        // x += g2 * (t1 @ f2w^T + f2b), fp16 single K=3072
        gemm_fp16<64, 0, 1, 0><<<dim3(12, 8), 256, SM64>>>(
            pt11, pw1 + OFF_FC2 + (size_t)d * E_DIM * MLP_DIM, fc2_b + d * E_DIM,
            px, pada + ao + 5 * E_DIM, px, nullptr, E_DIM, MLP_DIM);
    }
    k_lnmod<2><<<L_DIM, 256>>>(px, DEPTH * 6 * E_DIM);
    gemm_fp16<64, 0, 0, 0><<<dim3(12, 8), 256, SM64>>>(
        ph2, pw2 + OFF_FIN, fin_b, nullptr, nullptr, out, nullptr, E_DIM, K2E);
    (void)in_sizes; (void)n_in; (void)out_size;
}